// round 2
// baseline (speedup 1.0000x reference)
#include <cuda_runtime.h>
#include <cuda_bf16.h>

// ---------------- problem constants ----------------
#define NN   50000
#define EE   800000
#define RR   8
#define BB   4
#define FF   128            // in = hidden = 128
#define KB   (BB*FF)        // 512, basis-contracted K
#define EPSV 1e-5f

// ---------------- scratch (static device globals; no allocs) ----------------
__device__ float d_accB[NN * KB];          // [N, B*128] aggregated basis-folded messages
__device__ float d_xr[NN * FF];            // relu(bn(x1))
__device__ float d_rootskip[FF * FF];      // root + skip weight (per layer, rebuilt)
__device__ float d_biasc[FF];              // bias + skip bias
__device__ int   d_deg[NN];
__device__ int   d_off[NN + 1];
__device__ int   d_cursor[NN];
__device__ int   d_cnt[NN * RR];           // per (dst, relation) in-degree
__device__ int   d_esort[EE];              // CSR-sorted edges, packed (etype<<20)|src
__device__ int   d_chunksum[64];
__device__ float d_bnpart[2 * 200 * FF];
__device__ float d_scale[FF];
__device__ float d_shift[FF];

// ---------------- CSR build ----------------
__global__ void k_zero_meta() {
    int i = blockIdx.x * blockDim.x + threadIdx.x;
    int stride = gridDim.x * blockDim.x;
    for (int j = i; j < NN; j += stride) { d_deg[j] = 0; d_cursor[j] = 0; }
    for (int j = i; j < NN * RR; j += stride) d_cnt[j] = 0;
}

__global__ void k_count(const int* __restrict__ dst, const int* __restrict__ et) {
    int e = blockIdx.x * blockDim.x + threadIdx.x;
    if (e < EE) {
        int d = dst[e];
        int r = et[e];
        atomicAdd(&d_deg[d], 1);
        atomicAdd(&d_cnt[d * RR + r], 1);
    }
}

#define SCAN_CHUNK 1024
#define SCAN_NB    49    // ceil(50000/1024)

__global__ void k_scan_local() {
    __shared__ int sh[SCAN_CHUNK];
    int i = blockIdx.x * SCAN_CHUNK + threadIdx.x;
    int v = (i < NN) ? d_deg[i] : 0;
    sh[threadIdx.x] = v;
    __syncthreads();
    // Hillis-Steele inclusive scan
    for (int s = 1; s < SCAN_CHUNK; s <<= 1) {
        int t = (threadIdx.x >= s) ? sh[threadIdx.x - s] : 0;
        __syncthreads();
        sh[threadIdx.x] += t;
        __syncthreads();
    }
    if (i < NN) d_off[i] = sh[threadIdx.x] - v;   // exclusive within chunk
    if (threadIdx.x == SCAN_CHUNK - 1) d_chunksum[blockIdx.x] = sh[threadIdx.x];
}

__global__ void k_scan_chunks() {
    if (threadIdx.x == 0 && blockIdx.x == 0) {
        int acc = 0;
        for (int b = 0; b < SCAN_NB; b++) { int t = d_chunksum[b]; d_chunksum[b] = acc; acc += t; }
    }
}

__global__ void k_scan_add() {
    int i = blockIdx.x * SCAN_CHUNK + threadIdx.x;
    if (i < NN) d_off[i] += d_chunksum[blockIdx.x];
    if (i == 0) d_off[NN] = EE;
}

__global__ void k_scatter(const int* __restrict__ src, const int* __restrict__ dst,
                          const int* __restrict__ et) {
    int e = blockIdx.x * blockDim.x + threadIdx.x;
    if (e < EE) {
        int d = dst[e];
        int pos = d_off[d] + atomicAdd(&d_cursor[d], 1);
        d_esort[pos] = (et[e] << 20) | src[e];
    }
}

// ---------------- per-layer weight prep ----------------
__global__ void k_prep(const float* __restrict__ root, const float* __restrict__ skipw,
                       const float* __restrict__ bias, const float* __restrict__ skipb) {
    int i = blockIdx.x * blockDim.x + threadIdx.x;
    if (i < FF * FF) d_rootskip[i] = root[i] + skipw[i];
    if (i < FF)      d_biasc[i] = bias[i] + skipb[i];
}

// ---------------- aggregation: one block (128 thr) per node ----------------
// accB[node][b][f] = sum_edges x[src][f] * comp[et][b] / cnt[node, et]
__global__ void __launch_bounds__(128) k_agg(const float* __restrict__ xin,
                                             const float* __restrict__ comp) {
    __shared__ float sc[RR * BB];   // comp[r][b] / max(cnt[node,r],1)
    int node = blockIdx.x;
    int t = threadIdx.x;
    if (t < RR * BB) {
        int r = t >> 2;
        float c = (float)d_cnt[node * RR + r];
        sc[t] = comp[t] / fmaxf(c, 1.0f);
    }
    __syncthreads();
    int s = d_off[node], e = d_off[node + 1];
    float a0 = 0.f, a1 = 0.f, a2 = 0.f, a3 = 0.f;
    int i = s;
    for (; i + 4 <= e; i += 4) {
        int p0 = d_esort[i + 0], p1 = d_esort[i + 1];
        int p2 = d_esort[i + 2], p3 = d_esort[i + 3];
        int r0 = p0 >> 20, r1 = p1 >> 20, r2 = p2 >> 20, r3 = p3 >> 20;
        float v0 = xin[(p0 & 0xFFFFF) * FF + t];
        float v1 = xin[(p1 & 0xFFFFF) * FF + t];
        float v2 = xin[(p2 & 0xFFFFF) * FF + t];
        float v3 = xin[(p3 & 0xFFFFF) * FF + t];
        a0 += v0 * sc[r0 * 4 + 0] + v1 * sc[r1 * 4 + 0] + v2 * sc[r2 * 4 + 0] + v3 * sc[r3 * 4 + 0];
        a1 += v0 * sc[r0 * 4 + 1] + v1 * sc[r1 * 4 + 1] + v2 * sc[r2 * 4 + 1] + v3 * sc[r3 * 4 + 1];
        a2 += v0 * sc[r0 * 4 + 2] + v1 * sc[r1 * 4 + 2] + v2 * sc[r2 * 4 + 2] + v3 * sc[r3 * 4 + 2];
        a3 += v0 * sc[r0 * 4 + 3] + v1 * sc[r1 * 4 + 3] + v2 * sc[r2 * 4 + 3] + v3 * sc[r3 * 4 + 3];
    }
    for (; i < e; i++) {
        int p = d_esort[i];
        int r = p >> 20;
        float v = xin[(p & 0xFFFFF) * FF + t];
        a0 += v * sc[r * 4 + 0];
        a1 += v * sc[r * 4 + 1];
        a2 += v * sc[r * 4 + 2];
        a3 += v * sc[r * 4 + 3];
    }
    float* o = d_accB + node * KB + t;
    o[0 * FF] = a0; o[1 * FF] = a1; o[2 * FF] = a2; o[3 * FF] = a3;
}

// ---------------- fused GEMM: out = accB@bases + xin@(root+skip) + biasc ----------------
// A is logically [M, 640]: k<512 from accB (lda 512), k>=512 from xin (lda 128).
// Tiles: BM=128, BN=64, BK=32, 256 threads, micro 4x8.
#define BM 128
#define BN 64
#define BK 32

__global__ void __launch_bounds__(256) k_gemm(const float* __restrict__ A1,
                                              const float* __restrict__ A2,
                                              const float* __restrict__ B1,   // bases [512,128]
                                              const float* __restrict__ B2,   // rootskip [128,128]
                                              float* __restrict__ out) {
    __shared__ __align__(16) float As[BK][BM + 4];
    __shared__ __align__(16) float Bs[BK][BN];
    const int tid = threadIdx.x;
    const int m0 = blockIdx.x * BM;
    const int n0 = blockIdx.y * BN;
    const int ty = tid >> 3;    // 0..31 -> rows ty*4..ty*4+3
    const int tx = tid & 7;     // 0..7  -> cols tx*8..tx*8+7
    float acc[4][8];
#pragma unroll
    for (int r = 0; r < 4; r++)
#pragma unroll
        for (int c = 0; c < 8; c++) acc[r][c] = 0.f;

    for (int seg = 0; seg < 2; seg++) {
        const float* Ap = seg ? A2 : A1;
        const float* Bp = seg ? B2 : B1;
        const int lda = seg ? FF : KB;
        const int kseg = seg ? FF : KB;
        for (int kt = 0; kt < kseg; kt += BK) {
            // load A tile (128x32), store transposed into As[k][m]
#pragma unroll
            for (int j = 0; j < 4; j++) {
                int u = tid + 256 * j;          // 0..1023
                int row = u >> 3;               // 0..127
                int kc = (u & 7) << 2;          // 0,4,...,28
                float4 v = make_float4(0.f, 0.f, 0.f, 0.f);
                int gr = m0 + row;
                if (gr < NN)
                    v = *reinterpret_cast<const float4*>(Ap + (long)gr * lda + kt + kc);
                As[kc + 0][row] = v.x;
                As[kc + 1][row] = v.y;
                As[kc + 2][row] = v.z;
                As[kc + 3][row] = v.w;
            }
            // load B tile (32x64)
#pragma unroll
            for (int j = 0; j < 2; j++) {
                int u = tid + 256 * j;          // 0..511
                int row = u >> 4;               // 0..31
                int col = (u & 15) << 2;        // 0..60
                *reinterpret_cast<float4*>(&Bs[row][col]) =
                    *reinterpret_cast<const float4*>(Bp + (kt + row) * FF + n0 + col);
            }
            __syncthreads();
#pragma unroll
            for (int k = 0; k < BK; k++) {
                float4 af = *reinterpret_cast<const float4*>(&As[k][ty * 4]);
                float4 b0 = *reinterpret_cast<const float4*>(&Bs[k][tx * 8]);
                float4 b1 = *reinterpret_cast<const float4*>(&Bs[k][tx * 8 + 4]);
                float a_[4] = {af.x, af.y, af.z, af.w};
                float b_[8] = {b0.x, b0.y, b0.z, b0.w, b1.x, b1.y, b1.z, b1.w};
#pragma unroll
                for (int r = 0; r < 4; r++)
#pragma unroll
                    for (int c = 0; c < 8; c++) acc[r][c] += a_[r] * b_[c];
            }
            __syncthreads();
        }
    }
    // epilogue with combined bias
    float bsv[8];
#pragma unroll
    for (int c = 0; c < 8; c++) bsv[c] = d_biasc[n0 + tx * 8 + c];
#pragma unroll
    for (int r = 0; r < 4; r++) {
        int gr = m0 + ty * 4 + r;
        if (gr < NN) {
            float4 o0, o1;
            o0.x = acc[r][0] + bsv[0]; o0.y = acc[r][1] + bsv[1];
            o0.z = acc[r][2] + bsv[2]; o0.w = acc[r][3] + bsv[3];
            o1.x = acc[r][4] + bsv[4]; o1.y = acc[r][5] + bsv[5];
            o1.z = acc[r][6] + bsv[6]; o1.w = acc[r][7] + bsv[7];
            float* op = out + (long)gr * FF + n0 + tx * 8;
            *reinterpret_cast<float4*>(op) = o0;
            *reinterpret_cast<float4*>(op + 4) = o1;
        }
    }
}

// ---------------- BatchNorm (training stats) + ReLU ----------------
#define BN_NB 200
__global__ void k_bn_part(const float* __restrict__ x1) {
    int b = blockIdx.x;
    int t = threadIdx.x;
    int per = (NN + BN_NB - 1) / BN_NB;     // 250
    int r0 = b * per;
    int r1 = (r0 + per < NN) ? r0 + per : NN;
    float s = 0.f, q = 0.f;
    for (int r = r0; r < r1; r++) {
        float v = x1[(long)r * FF + t];
        s += v;
        q += v * v;
    }
    d_bnpart[b * FF + t] = s;
    d_bnpart[BN_NB * FF + b * FF + t] = q;
}

__global__ void k_bn_final(const float* __restrict__ gamma, const float* __restrict__ beta) {
    int t = threadIdx.x;
    float s = 0.f, q = 0.f;
    for (int b = 0; b < BN_NB; b++) {
        s += d_bnpart[b * FF + t];
        q += d_bnpart[BN_NB * FF + b * FF + t];
    }
    float mean = s / (float)NN;
    float var = q / (float)NN - mean * mean;
    float inv = rsqrtf(var + EPSV);
    float sc = gamma[t] * inv;
    d_scale[t] = sc;
    d_shift[t] = beta[t] - mean * sc;
}

__global__ void k_bn_apply(const float* __restrict__ x1) {
    long i = (long)blockIdx.x * blockDim.x + threadIdx.x;
    if (i < (long)NN * FF) {
        int c = (int)(i & (FF - 1));
        float v = x1[i] * d_scale[c] + d_shift[c];
        d_xr[i] = fmaxf(v, 0.f);
    }
}

// ---------------- launch ----------------
extern "C" void kernel_launch(void* const* d_in, const int* in_sizes, int n_in,
                              void* d_out, int out_size) {
    const float* x      = (const float*)d_in[0];
    const int*   ei     = (const int*)d_in[1];     // [2, E]
    const int*   etype  = (const int*)d_in[2];
    const float* comp1  = (const float*)d_in[3];
    const float* bases1 = (const float*)d_in[4];
    const float* root1  = (const float*)d_in[5];
    const float* bias1  = (const float*)d_in[6];
    const float* skip1w = (const float*)d_in[7];
    const float* skip1b = (const float*)d_in[8];
    const float* gamma  = (const float*)d_in[9];
    const float* beta   = (const float*)d_in[10];
    const float* comp2  = (const float*)d_in[11];
    const float* bases2 = (const float*)d_in[12];
    const float* root2  = (const float*)d_in[13];
    const float* bias2  = (const float*)d_in[14];
    const float* skip2w = (const float*)d_in[15];
    const float* skip2b = (const float*)d_in[16];

    float* h_out  = (float*)d_out;                // x1 pre-BN
    float* x2_out = (float*)d_out + (long)NN * FF;

    const int* src = ei;
    const int* dst = ei + EE;

    // get scratch addresses for kernels that need raw pointers
    float* accB = nullptr;
    float* xr   = nullptr;
    cudaGetSymbolAddress((void**)&accB, d_accB);
    cudaGetSymbolAddress((void**)&xr, d_xr);
    float* rootskip = nullptr;
    cudaGetSymbolAddress((void**)&rootskip, d_rootskip);

    const int EB = (EE + 255) / 256;

    // ---- CSR build (shared by both layers) ----
    k_zero_meta<<<1600, 256>>>();
    k_count<<<EB, 256>>>(dst, etype);
    k_scan_local<<<SCAN_NB, SCAN_CHUNK>>>();
    k_scan_chunks<<<1, 32>>>();
    k_scan_add<<<SCAN_NB, SCAN_CHUNK>>>();
    k_scatter<<<EB, 256>>>(src, dst, etype);

    dim3 gemm_grid((NN + BM - 1) / BM, FF / BN);

    // ---- layer 1 ----
    k_prep<<<(FF * FF + 127) / 128, 128>>>(root1, skip1w, bias1, skip1b);
    k_agg<<<NN, 128>>>(x, comp1);
    k_gemm<<<gemm_grid, 256>>>(accB, x, bases1, rootskip, h_out);

    // ---- BN + ReLU ----
    k_bn_part<<<BN_NB, FF>>>(h_out);
    k_bn_final<<<1, FF>>>(gamma, beta);
    k_bn_apply<<<(NN * FF + 255) / 256, 256>>>(h_out);

    // ---- layer 2 ----
    k_prep<<<(FF * FF + 127) / 128, 128>>>(root2, skip2w, bias2, skip2b);
    k_agg<<<NN, 128>>>(xr, comp2);
    k_gemm<<<gemm_grid, 256>>>(accB, xr, bases2, rootskip, x2_out);
}

// round 4
// speedup vs baseline: 2.3567x; 2.3567x over previous
#include <cuda_runtime.h>
#include <cuda_bf16.h>
#include <cstdint>

// ---------------- problem constants ----------------
#define NN   50000
#define EE   800000
#define RR   8
#define BB   4
#define FF   128            // in = hidden = 128
#define KB   (BB*FF)        // 512, basis-contracted K
#define GK   640            // total GEMM K = 512 (accB) + 128 (x)
#define EPSV 1e-5f

// ---------------- scratch (static device globals; no allocs) ----------------
__device__ __nv_bfloat16 d_accBh[NN * KB];   // aggregated messages, bf16 hi
__device__ __nv_bfloat16 d_accBl[NN * KB];   // bf16 lo residual
__device__ __nv_bfloat16 d_xh[NN * FF];      // split of layer-1 input x
__device__ __nv_bfloat16 d_xl[NN * FF];
__device__ __nv_bfloat16 d_xrh[NN * FF];     // split of relu(bn(x1))
__device__ __nv_bfloat16 d_xrl[NN * FF];
__device__ float d_xr[NN * FF];              // fp32 relu(bn(x1)) for aggregation
__device__ __nv_bfloat16 d_Wbh[FF * GK];     // weight, [n][k], bf16 hi
__device__ __nv_bfloat16 d_Wbl[FF * GK];     // bf16 lo
__device__ float d_biasc[FF];
__device__ int   d_deg[NN];
__device__ int   d_off[NN + 1];
__device__ int   d_cursor[NN];
__device__ int   d_cnt[NN * RR];
__device__ int   d_esort[EE];                // packed (etype<<20)|src
__device__ int   d_chunksum[64];
__device__ float d_bnpart[2 * 200 * FF];
__device__ float d_scale[FF];
__device__ float d_shift[FF];

// ---------------- helpers ----------------
__device__ __forceinline__ uint32_t smem_u32(const void* p) {
    uint32_t a;
    asm("{ .reg .u64 t; cvta.to.shared.u64 t, %1; cvt.u32.u64 %0, t; }" : "=r"(a) : "l"(p));
    return a;
}
__device__ __forceinline__ uint32_t lds32(uint32_t a) {
    uint32_t v;
    asm volatile("ld.shared.b32 %0, [%1];" : "=r"(v) : "r"(a));
    return v;
}
__device__ __forceinline__ void cp16(uint32_t dst, const void* src, int szbytes) {
    asm volatile("cp.async.cg.shared.global [%0], [%1], 16, %2;"
                 :: "r"(dst), "l"(src), "r"(szbytes) : "memory");
}
#define CP_COMMIT() asm volatile("cp.async.commit_group;" ::: "memory")
#define CP_WAIT1()  asm volatile("cp.async.wait_group 1;" ::: "memory")
#define CP_WAIT0()  asm volatile("cp.async.wait_group 0;" ::: "memory")

#define MMA_BF16(acc, a, b)                                                   \
    asm volatile(                                                             \
        "mma.sync.aligned.m16n8k16.row.col.f32.bf16.bf16.f32 "                \
        "{%0,%1,%2,%3}, {%4,%5,%6,%7}, {%8,%9}, {%0,%1,%2,%3};"               \
        : "+f"((acc)[0]), "+f"((acc)[1]), "+f"((acc)[2]), "+f"((acc)[3])      \
        : "r"((a)[0]), "r"((a)[1]), "r"((a)[2]), "r"((a)[3]),                 \
          "r"((b)[0]), "r"((b)[1]))

// ---------------- CSR build ----------------
__global__ void k_zero_meta() {
    int i = blockIdx.x * blockDim.x + threadIdx.x;
    int stride = gridDim.x * blockDim.x;
    for (int j = i; j < NN; j += stride) { d_deg[j] = 0; d_cursor[j] = 0; }
    for (int j = i; j < NN * RR; j += stride) d_cnt[j] = 0;
}

__global__ void k_count(const int* __restrict__ dst, const int* __restrict__ et) {
    int e = blockIdx.x * blockDim.x + threadIdx.x;
    if (e < EE) {
        int d = dst[e];
        int r = et[e];
        atomicAdd(&d_deg[d], 1);
        atomicAdd(&d_cnt[d * RR + r], 1);
    }
}

#define SCAN_CHUNK 1024
#define SCAN_NB    49

__global__ void k_scan_local() {
    __shared__ int sh[SCAN_CHUNK];
    int i = blockIdx.x * SCAN_CHUNK + threadIdx.x;
    int v = (i < NN) ? d_deg[i] : 0;
    sh[threadIdx.x] = v;
    __syncthreads();
    for (int s = 1; s < SCAN_CHUNK; s <<= 1) {
        int t = (threadIdx.x >= s) ? sh[threadIdx.x - s] : 0;
        __syncthreads();
        sh[threadIdx.x] += t;
        __syncthreads();
    }
    if (i < NN) d_off[i] = sh[threadIdx.x] - v;
    if (threadIdx.x == SCAN_CHUNK - 1) d_chunksum[blockIdx.x] = sh[threadIdx.x];
}

__global__ void k_scan_chunks() {
    if (threadIdx.x == 0 && blockIdx.x == 0) {
        int acc = 0;
        for (int b = 0; b < SCAN_NB; b++) { int t = d_chunksum[b]; d_chunksum[b] = acc; acc += t; }
    }
}

__global__ void k_scan_add() {
    int i = blockIdx.x * SCAN_CHUNK + threadIdx.x;
    if (i < NN) d_off[i] += d_chunksum[blockIdx.x];
    if (i == 0) d_off[NN] = EE;
}

__global__ void k_scatter(const int* __restrict__ src, const int* __restrict__ dst,
                          const int* __restrict__ et) {
    int e = blockIdx.x * blockDim.x + threadIdx.x;
    if (e < EE) {
        int d = dst[e];
        int pos = d_off[d] + atomicAdd(&d_cursor[d], 1);
        d_esort[pos] = (et[e] << 20) | src[e];
    }
}

// ---------------- per-layer weight prep: [n][k] bf16 hi/lo ----------------
__global__ void k_prep(const float* __restrict__ root, const float* __restrict__ skipw,
                       const float* __restrict__ bias, const float* __restrict__ skipb,
                       const float* __restrict__ bases) {
    int k = blockIdx.x;
    int n = threadIdx.x;
    float w = (k < KB) ? bases[k * FF + n]
                       : root[(k - KB) * FF + n] + skipw[(k - KB) * FF + n];
    __nv_bfloat16 h = __float2bfloat16(w);
    d_Wbh[n * GK + k] = h;
    d_Wbl[n * GK + k] = __float2bfloat16(w - __bfloat162float(h));
    if (k == 0) d_biasc[n] = bias[n] + skipb[n];
}

// ---------------- split fp32 -> bf16 hi/lo ----------------
__global__ void k_split_x(const float* __restrict__ x) {
    long i = (long)blockIdx.x * blockDim.x + threadIdx.x;
    if (i < (long)NN * FF) {
        float v = x[i];
        __nv_bfloat16 h = __float2bfloat16(v);
        d_xh[i] = h;
        d_xl[i] = __float2bfloat16(v - __bfloat162float(h));
    }
}

// ---------------- aggregation: one block (128 thr) per node ----------------
__global__ void __launch_bounds__(128) k_agg(const float* __restrict__ xin,
                                             const float* __restrict__ comp) {
    __shared__ float sc[RR * BB];
    int node = blockIdx.x;
    int t = threadIdx.x;
    if (t < RR * BB) {
        int r = t >> 2;
        float c = (float)d_cnt[node * RR + r];
        sc[t] = comp[t] / fmaxf(c, 1.0f);
    }
    __syncthreads();
    int s = d_off[node], e = d_off[node + 1];
    float a0 = 0.f, a1 = 0.f, a2 = 0.f, a3 = 0.f;
    int i = s;
    for (; i + 4 <= e; i += 4) {
        int p0 = d_esort[i + 0], p1 = d_esort[i + 1];
        int p2 = d_esort[i + 2], p3 = d_esort[i + 3];
        int r0 = p0 >> 20, r1 = p1 >> 20, r2 = p2 >> 20, r3 = p3 >> 20;
        float v0 = xin[(p0 & 0xFFFFF) * FF + t];
        float v1 = xin[(p1 & 0xFFFFF) * FF + t];
        float v2 = xin[(p2 & 0xFFFFF) * FF + t];
        float v3 = xin[(p3 & 0xFFFFF) * FF + t];
        a0 += v0 * sc[r0 * 4 + 0] + v1 * sc[r1 * 4 + 0] + v2 * sc[r2 * 4 + 0] + v3 * sc[r3 * 4 + 0];
        a1 += v0 * sc[r0 * 4 + 1] + v1 * sc[r1 * 4 + 1] + v2 * sc[r2 * 4 + 1] + v3 * sc[r3 * 4 + 1];
        a2 += v0 * sc[r0 * 4 + 2] + v1 * sc[r1 * 4 + 2] + v2 * sc[r2 * 4 + 2] + v3 * sc[r3 * 4 + 2];
        a3 += v0 * sc[r0 * 4 + 3] + v1 * sc[r1 * 4 + 3] + v2 * sc[r2 * 4 + 3] + v3 * sc[r3 * 4 + 3];
    }
    for (; i < e; i++) {
        int p = d_esort[i];
        int r = p >> 20;
        float v = xin[(p & 0xFFFFF) * FF + t];
        a0 += v * sc[r * 4 + 0];
        a1 += v * sc[r * 4 + 1];
        a2 += v * sc[r * 4 + 2];
        a3 += v * sc[r * 4 + 3];
    }
    float vals[4] = {a0, a1, a2, a3};
    long base = (long)node * KB + t;
#pragma unroll
    for (int b = 0; b < 4; b++) {
        __nv_bfloat16 h = __float2bfloat16(vals[b]);
        d_accBh[base + b * FF] = h;
        d_accBl[base + b * FF] = __float2bfloat16(vals[b] - __bfloat162float(h));
    }
}

// ---------------- mma.sync bf16 GEMM with 3-term split ----------------
// out[m][n] = sum_k A[m][k]*W[k][n] + biasc[n];  A = [accB | x], K = 640
// CTA tile 128x128, BK=64, 8 warps (4 M x 2 N), warp tile 32x64.
// SMEM per stage: Ah,Al (128x64 bf16, 16KB each) + Bh,Bl (128x64, 16KB each) = 64KB.
#define BKC     64
#define NCHUNK  10
#define TILE_B  16384
#define STAGE_B 65536
#define GEMM_SMEM (2 * STAGE_B)

__device__ __forceinline__ void prefetch_chunk(
        int cNum, uint32_t sbase, int m0, int tid,
        const __nv_bfloat16* Ah, const __nv_bfloat16* Al,
        const __nv_bfloat16* AtH, const __nv_bfloat16* AtL) {
    const __nv_bfloat16 *ah, *al;
    int lda, kofs;
    if (cNum < 8) { ah = Ah;  al = Al;  lda = KB; kofs = cNum * BKC; }
    else          { ah = AtH; al = AtL; lda = FF; kofs = (cNum - 8) * BKC; }
#pragma unroll
    for (int i = 0; i < 4; i++) {
        int idx = tid + i * 256;        // 0..1023
        int r = idx >> 3;               // 0..127
        int c = idx & 7;                // 16B chunk within 128B row
        uint32_t sw = (uint32_t)((c ^ (r & 7)) << 4);
        int gr = m0 + r;
        int sz = (gr < NN) ? 16 : 0;
        int grc = (gr < NN) ? gr : 0;
        long aofs = (long)grc * lda + kofs + c * 8;
        uint32_t dst = sbase + r * 128 + sw;
        cp16(dst,              ah + aofs, sz);
        cp16(dst + TILE_B,     al + aofs, sz);
        long bofs = (long)r * GK + cNum * BKC + c * 8;
        uint32_t dstB = sbase + 2 * TILE_B + r * 128 + sw;
        cp16(dstB,             d_Wbh + bofs, 16);
        cp16(dstB + TILE_B,    d_Wbl + bofs, 16);
    }
}

__global__ void __launch_bounds__(256) k_gemm_mma(
        const __nv_bfloat16* __restrict__ Ah, const __nv_bfloat16* __restrict__ Al,
        const __nv_bfloat16* __restrict__ AtH, const __nv_bfloat16* __restrict__ AtL,
        float* __restrict__ out) {
    extern __shared__ float4 smem_raw[];
    uint32_t sm0 = smem_u32(smem_raw);
    const int tid = threadIdx.x;
    const int wid = tid >> 5;
    const int lane = tid & 31;
    const int m0 = blockIdx.x * 128;
    const int warp_m = (wid & 3) * 32;
    const int warp_n = (wid >> 2) * 64;
    const int g = lane >> 2;
    const int t = lane & 3;

    float acc[2][8][4];
#pragma unroll
    for (int mt = 0; mt < 2; mt++)
#pragma unroll
        for (int nt = 0; nt < 8; nt++)
#pragma unroll
            for (int q = 0; q < 4; q++) acc[mt][nt][q] = 0.f;

    prefetch_chunk(0, sm0, m0, tid, Ah, Al, AtH, AtL);
    CP_COMMIT();

#pragma unroll 1
    for (int c = 0; c < NCHUNK; c++) {
        if (c + 1 < NCHUNK) {
            prefetch_chunk(c + 1, sm0 + ((c + 1) & 1) * STAGE_B, m0, tid, Ah, Al, AtH, AtL);
            CP_COMMIT();
            CP_WAIT1();
        } else {
            CP_WAIT0();
        }
        __syncthreads();
        const uint32_t su = sm0 + (c & 1) * STAGE_B;
#pragma unroll
        for (int s = 0; s < 4; s++) {
            const int c0 = s * 2;                              // 16B chunk index of k16 base
            const uint32_t swA = (uint32_t)(((c0 ^ g) << 4) + t * 4);
            const uint32_t swB = (uint32_t)((((c0 + 1) ^ g) << 4) + t * 4);
            uint32_t a_h[2][4], a_l[2][4];
#pragma unroll
            for (int mt = 0; mt < 2; mt++) {
                const uint32_t rb  = su + (warp_m + mt * 16 + g) * 128;
                const uint32_t rb8 = rb + 8 * 128;
                a_h[mt][0] = lds32(rb + swA);
                a_h[mt][1] = lds32(rb8 + swA);
                a_h[mt][2] = lds32(rb + swB);
                a_h[mt][3] = lds32(rb8 + swB);
                a_l[mt][0] = lds32(rb + TILE_B + swA);
                a_l[mt][1] = lds32(rb8 + TILE_B + swA);
                a_l[mt][2] = lds32(rb + TILE_B + swB);
                a_l[mt][3] = lds32(rb8 + TILE_B + swB);
            }
#pragma unroll
            for (int nt = 0; nt < 8; nt++) {
                const uint32_t nb = su + 2 * TILE_B + (warp_n + nt * 8 + g) * 128;
                uint32_t b_h[2], b_l[2];
                b_h[0] = lds32(nb + swA);
                b_h[1] = lds32(nb + swB);
                b_l[0] = lds32(nb + TILE_B + swA);
                b_l[1] = lds32(nb + TILE_B + swB);
#pragma unroll
                for (int mt = 0; mt < 2; mt++) {
                    MMA_BF16(acc[mt][nt], a_h[mt], b_h);
                    MMA_BF16(acc[mt][nt], a_l[mt], b_h);
                    MMA_BF16(acc[mt][nt], a_h[mt], b_l);
                }
            }
        }
        __syncthreads();
    }

    // epilogue: bias + store
#pragma unroll
    for (int mt = 0; mt < 2; mt++) {
        const int r0 = m0 + warp_m + mt * 16 + g;
#pragma unroll
        for (int nt = 0; nt < 8; nt++) {
            const int col = warp_n + nt * 8 + t * 2;
            const float b0 = d_biasc[col];
            const float b1 = d_biasc[col + 1];
            if (r0 < NN) {
                float2 o = make_float2(acc[mt][nt][0] + b0, acc[mt][nt][1] + b1);
                *reinterpret_cast<float2*>(out + (long)r0 * FF + col) = o;
            }
            if (r0 + 8 < NN) {
                float2 o = make_float2(acc[mt][nt][2] + b0, acc[mt][nt][3] + b1);
                *reinterpret_cast<float2*>(out + (long)(r0 + 8) * FF + col) = o;
            }
        }
    }
}

// ---------------- BatchNorm (training stats) + ReLU ----------------
#define BN_NB 200
__global__ void k_bn_part(const float* __restrict__ x1) {
    int b = blockIdx.x;
    int t = threadIdx.x;
    int per = (NN + BN_NB - 1) / BN_NB;
    int r0 = b * per;
    int r1 = (r0 + per < NN) ? r0 + per : NN;
    float s = 0.f, q = 0.f;
    for (int r = r0; r < r1; r++) {
        float v = x1[(long)r * FF + t];
        s += v;
        q += v * v;
    }
    d_bnpart[b * FF + t] = s;
    d_bnpart[BN_NB * FF + b * FF + t] = q;
}

__global__ void k_bn_final(const float* __restrict__ gamma, const float* __restrict__ beta) {
    int t = threadIdx.x;
    float s = 0.f, q = 0.f;
    for (int b = 0; b < BN_NB; b++) {
        s += d_bnpart[b * FF + t];
        q += d_bnpart[BN_NB * FF + b * FF + t];
    }
    float mean = s / (float)NN;
    float var = q / (float)NN - mean * mean;
    float inv = rsqrtf(var + EPSV);
    float sc = gamma[t] * inv;
    d_scale[t] = sc;
    d_shift[t] = beta[t] - mean * sc;
}

__global__ void k_bn_apply(const float* __restrict__ x1) {
    long i = (long)blockIdx.x * blockDim.x + threadIdx.x;
    if (i < (long)NN * FF) {
        int c = (int)(i & (FF - 1));
        float v = fmaxf(x1[i] * d_scale[c] + d_shift[c], 0.f);
        d_xr[i] = v;
        __nv_bfloat16 h = __float2bfloat16(v);
        d_xrh[i] = h;
        d_xrl[i] = __float2bfloat16(v - __bfloat162float(h));
    }
}

// ---------------- launch ----------------
extern "C" void kernel_launch(void* const* d_in, const int* in_sizes, int n_in,
                              void* d_out, int out_size) {
    const float* x      = (const float*)d_in[0];
    const int*   ei     = (const int*)d_in[1];
    const int*   etype  = (const int*)d_in[2];
    const float* comp1  = (const float*)d_in[3];
    const float* bases1 = (const float*)d_in[4];
    const float* root1  = (const float*)d_in[5];
    const float* bias1  = (const float*)d_in[6];
    const float* skip1w = (const float*)d_in[7];
    const float* skip1b = (const float*)d_in[8];
    const float* gamma  = (const float*)d_in[9];
    const float* beta   = (const float*)d_in[10];
    const float* comp2  = (const float*)d_in[11];
    const float* bases2 = (const float*)d_in[12];
    const float* root2  = (const float*)d_in[13];
    const float* bias2  = (const float*)d_in[14];
    const float* skip2w = (const float*)d_in[15];
    const float* skip2b = (const float*)d_in[16];

    float* h_out  = (float*)d_out;                // x1 pre-BN
    float* x2_out = (float*)d_out + (long)NN * FF;

    const int* src = ei;
    const int* dst = ei + EE;

    __nv_bfloat16 *accBh, *accBl, *xh, *xl, *xrh, *xrl;
    float* xr;
    cudaGetSymbolAddress((void**)&accBh, d_accBh);
    cudaGetSymbolAddress((void**)&accBl, d_accBl);
    cudaGetSymbolAddress((void**)&xh, d_xh);
    cudaGetSymbolAddress((void**)&xl, d_xl);
    cudaGetSymbolAddress((void**)&xrh, d_xrh);
    cudaGetSymbolAddress((void**)&xrl, d_xrl);
    cudaGetSymbolAddress((void**)&xr, d_xr);

    static bool attr_done = false;
    if (!attr_done) {
        cudaFuncSetAttribute(k_gemm_mma, cudaFuncAttributeMaxDynamicSharedMemorySize, GEMM_SMEM);
        attr_done = true;
    }

    const int EB = (EE + 255) / 256;
    const int NB = (NN * FF + 255) / 256;

    // ---- CSR build (shared by both layers) ----
    k_zero_meta<<<1600, 256>>>();
    k_count<<<EB, 256>>>(dst, etype);
    k_scan_local<<<SCAN_NB, SCAN_CHUNK>>>();
    k_scan_chunks<<<1, 32>>>();
    k_scan_add<<<SCAN_NB, SCAN_CHUNK>>>();
    k_scatter<<<EB, 256>>>(src, dst, etype);

    const int GEMM_GRID = (NN + 127) / 128;

    // ---- layer 1 ----
    k_split_x<<<NB, 256>>>(x);
    k_prep<<<GK, FF>>>(root1, skip1w, bias1, skip1b, bases1);
    k_agg<<<NN, 128>>>(x, comp1);
    k_gemm_mma<<<GEMM_GRID, 256, GEMM_SMEM>>>(accBh, accBl, xh, xl, h_out);

    // ---- BN + ReLU ----
    k_bn_part<<<BN_NB, FF>>>(h_out);
    k_bn_final<<<1, FF>>>(gamma, beta);
    k_bn_apply<<<NB, 256>>>(h_out);

    // ---- layer 2 ----
    k_prep<<<GK, FF>>>(root2, skip2w, bias2, skip2b, bases2);
    k_agg<<<NN, 128>>>(xr, comp2);
    k_gemm_mma<<<GEMM_GRID, 256, GEMM_SMEM>>>(accBh, accBl, xrh, xrl, x2_out);
}

// round 9
// speedup vs baseline: 2.4209x; 1.0272x over previous
#include <cuda_runtime.h>
#include <cuda_bf16.h>
#include <cstdint>

// ---------------- problem constants ----------------
#define NN   50000
#define EE   800000
#define RR   8
#define BB   4
#define FF   128            // in = hidden = 128
#define KB   (BB*FF)        // 512, basis-contracted K
#define GK   640            // total GEMM K = 512 (accB) + 128 (x)
#define EPSV 1e-5f

// ---------------- scratch (static device globals; no allocs) ----------------
__device__ __nv_bfloat16 d_accBh[NN * KB];   // aggregated messages, bf16 hi
__device__ __nv_bfloat16 d_accBl[NN * KB];   // bf16 lo residual
__device__ __nv_bfloat16 d_xh[NN * FF];      // split of layer-1 input x
__device__ __nv_bfloat16 d_xl[NN * FF];
__device__ __nv_bfloat16 d_xrh[NN * FF];     // split of relu(bn(x1))
__device__ __nv_bfloat16 d_xrl[NN * FF];
__device__ float d_xr[NN * FF];              // fp32 relu(bn(x1)) for aggregation
__device__ __nv_bfloat16 d_Wbh1[FF * GK];    // layer-1 weight, [n][k], bf16 hi
__device__ __nv_bfloat16 d_Wbl1[FF * GK];
__device__ __nv_bfloat16 d_Wbh2[FF * GK];    // layer-2 weight
__device__ __nv_bfloat16 d_Wbl2[FF * GK];
__device__ float d_biasc1[FF];
__device__ float d_biasc2[FF];
__device__ int   d_off[NN + 1];
__device__ int   d_cursor[NN];
__device__ int   d_cnt[NN * RR];
__device__ int   d_esort[EE];                // packed (etype<<20)|src
__device__ int   d_chunksum[64];
__device__ float d_bnpart[2 * 200 * FF];
__device__ float d_scale[FF];
__device__ float d_shift[FF];

// ---------------- helpers ----------------
__device__ __forceinline__ uint32_t smem_u32(const void* p) {
    uint32_t a;
    asm("{ .reg .u64 t; cvta.to.shared.u64 t, %1; cvt.u32.u64 %0, t; }" : "=r"(a) : "l"(p));
    return a;
}
__device__ __forceinline__ void cp16(uint32_t dst, const void* src, int szbytes) {
    asm volatile("cp.async.cg.shared.global [%0], [%1], 16, %2;"
                 :: "r"(dst), "l"(src), "r"(szbytes) : "memory");
}
#define CP_COMMIT() asm volatile("cp.async.commit_group;" ::: "memory")
#define CP_WAIT1()  asm volatile("cp.async.wait_group 1;" ::: "memory")
#define CP_WAIT0()  asm volatile("cp.async.wait_group 0;" ::: "memory")

#define LDSM4(R, addr)                                                        \
    asm volatile("ldmatrix.sync.aligned.m8n8.x4.shared.b16 {%0,%1,%2,%3}, [%4];" \
                 : "=r"((R)[0]), "=r"((R)[1]), "=r"((R)[2]), "=r"((R)[3])     \
                 : "r"(addr))

#define MMA_BF16(acc, a, b)                                                   \
    asm volatile(                                                             \
        "mma.sync.aligned.m16n8k16.row.col.f32.bf16.bf16.f32 "                \
        "{%0,%1,%2,%3}, {%4,%5,%6,%7}, {%8,%9}, {%0,%1,%2,%3};"               \
        : "+f"((acc)[0]), "+f"((acc)[1]), "+f"((acc)[2]), "+f"((acc)[3])      \
        : "r"((a)[0]), "r"((a)[1]), "r"((a)[2]), "r"((a)[3]),                 \
          "r"((b)[0]), "r"((b)[1]))

// ---------------- CSR build ----------------
__global__ void k_zero_meta() {
    int i = blockIdx.x * blockDim.x + threadIdx.x;
    int stride = gridDim.x * blockDim.x;
    for (int j = i; j < NN; j += stride) d_cursor[j] = 0;
    for (int j = i; j < NN * RR; j += stride) d_cnt[j] = 0;
}

__global__ void k_count(const int* __restrict__ dst, const int* __restrict__ et) {
    int e = blockIdx.x * blockDim.x + threadIdx.x;
    if (e < EE) atomicAdd(&d_cnt[dst[e] * RR + et[e]], 1);
}

#define SCAN_CHUNK 1024
#define SCAN_NB    49

__global__ void k_scan_local() {
    __shared__ int sh[SCAN_CHUNK];
    int i = blockIdx.x * SCAN_CHUNK + threadIdx.x;
    int v = 0;
    if (i < NN) {
#pragma unroll
        for (int r = 0; r < RR; r++) v += d_cnt[i * RR + r];
    }
    sh[threadIdx.x] = v;
    __syncthreads();
    for (int s = 1; s < SCAN_CHUNK; s <<= 1) {
        int t = (threadIdx.x >= s) ? sh[threadIdx.x - s] : 0;
        __syncthreads();
        sh[threadIdx.x] += t;
        __syncthreads();
    }
    if (i < NN) d_off[i] = sh[threadIdx.x] - v;
    if (threadIdx.x == SCAN_CHUNK - 1) d_chunksum[blockIdx.x] = sh[threadIdx.x];
}

__global__ void k_scan_chunks() {
    if (threadIdx.x == 0 && blockIdx.x == 0) {
        int acc = 0;
        for (int b = 0; b < SCAN_NB; b++) { int t = d_chunksum[b]; d_chunksum[b] = acc; acc += t; }
    }
}

__global__ void k_scan_add() {
    int i = blockIdx.x * SCAN_CHUNK + threadIdx.x;
    if (i < NN) d_off[i] += d_chunksum[blockIdx.x];
    if (i == 0) d_off[NN] = EE;
}

__global__ void k_scatter(const int* __restrict__ src, const int* __restrict__ dst,
                          const int* __restrict__ et) {
    int e = blockIdx.x * blockDim.x + threadIdx.x;
    if (e < EE) {
        int d = dst[e];
        int pos = d_off[d] + atomicAdd(&d_cursor[d], 1);
        d_esort[pos] = (et[e] << 20) | src[e];
    }
}

// ---------------- per-layer weight prep: [n][k] bf16 hi/lo ----------------
__global__ void k_prep(const float* __restrict__ root, const float* __restrict__ skipw,
                       const float* __restrict__ bias, const float* __restrict__ skipb,
                       const float* __restrict__ bases,
                       __nv_bfloat16* __restrict__ Wh, __nv_bfloat16* __restrict__ Wl,
                       float* __restrict__ biasc) {
    int k = blockIdx.x;
    int n = threadIdx.x;
    float w = (k < KB) ? bases[k * FF + n]
                       : root[(k - KB) * FF + n] + skipw[(k - KB) * FF + n];
    __nv_bfloat16 h = __float2bfloat16(w);
    Wh[n * GK + k] = h;
    Wl[n * GK + k] = __float2bfloat16(w - __bfloat162float(h));
    if (k == 0) biasc[n] = bias[n] + skipb[n];
}

// ---------------- split fp32 -> bf16 hi/lo ----------------
__global__ void k_split_x(const float* __restrict__ x) {
    long i = (long)blockIdx.x * blockDim.x + threadIdx.x;
    if (i < (long)NN * FF) {
        float v = x[i];
        __nv_bfloat16 h = __float2bfloat16(v);
        d_xh[i] = h;
        d_xl[i] = __float2bfloat16(v - __bfloat162float(h));
    }
}

// ---------------- aggregation: one block (128 thr) per node ----------------
__global__ void __launch_bounds__(128) k_agg(const float* __restrict__ xin,
                                             const float* __restrict__ comp) {
    __shared__ float sc[RR * BB];
    int node = blockIdx.x;
    int t = threadIdx.x;
    if (t < RR * BB) {
        int r = t >> 2;
        float c = (float)d_cnt[node * RR + r];
        sc[t] = comp[t] / fmaxf(c, 1.0f);
    }
    __syncthreads();
    int s = d_off[node], e = d_off[node + 1];
    float a0 = 0.f, a1 = 0.f, a2 = 0.f, a3 = 0.f;
    int i = s;
    for (; i + 4 <= e; i += 4) {
        int p0 = d_esort[i + 0], p1 = d_esort[i + 1];
        int p2 = d_esort[i + 2], p3 = d_esort[i + 3];
        int r0 = p0 >> 20, r1 = p1 >> 20, r2 = p2 >> 20, r3 = p3 >> 20;
        float v0 = xin[(p0 & 0xFFFFF) * FF + t];
        float v1 = xin[(p1 & 0xFFFFF) * FF + t];
        float v2 = xin[(p2 & 0xFFFFF) * FF + t];
        float v3 = xin[(p3 & 0xFFFFF) * FF + t];
        a0 += v0 * sc[r0 * 4 + 0] + v1 * sc[r1 * 4 + 0] + v2 * sc[r2 * 4 + 0] + v3 * sc[r3 * 4 + 0];
        a1 += v0 * sc[r0 * 4 + 1] + v1 * sc[r1 * 4 + 1] + v2 * sc[r2 * 4 + 1] + v3 * sc[r3 * 4 + 1];
        a2 += v0 * sc[r0 * 4 + 2] + v1 * sc[r1 * 4 + 2] + v2 * sc[r2 * 4 + 2] + v3 * sc[r3 * 4 + 2];
        a3 += v0 * sc[r0 * 4 + 3] + v1 * sc[r1 * 4 + 3] + v2 * sc[r2 * 4 + 3] + v3 * sc[r3 * 4 + 3];
    }
    for (; i < e; i++) {
        int p = d_esort[i];
        int r = p >> 20;
        float v = xin[(p & 0xFFFFF) * FF + t];
        a0 += v * sc[r * 4 + 0];
        a1 += v * sc[r * 4 + 1];
        a2 += v * sc[r * 4 + 2];
        a3 += v * sc[r * 4 + 3];
    }
    float vals[4] = {a0, a1, a2, a3};
    long base = (long)node * KB + t;
#pragma unroll
    for (int b = 0; b < 4; b++) {
        __nv_bfloat16 h = __float2bfloat16(vals[b]);
        d_accBh[base + b * FF] = h;
        d_accBl[base + b * FF] = __float2bfloat16(vals[b] - __bfloat162float(h));
    }
}

// ---------------- mma.sync bf16 GEMM with 3-term split + ldmatrix ----------------
// out[m][n] = sum_k A[m][k]*W[k][n] + biasc[n];  A = [accB | x], K = 640
// CTA tile 128x128, BK=32, 8 warps (4 M x 2 N), warp tile 32x64, 2 CTAs/SM.
// SMEM per stage: Ah,Al,Bh,Bl tiles of 128x32 bf16 (8KB each) = 32KB; 2 stages.
// Swizzle: 64B rows; 16B slot = (chunk ^ ((row>>1)&3)).
#define BKC     32
#define NCHUNK  20
#define TILE_B  8192
#define STAGE_B 32768
#define GEMM_SMEM (2 * STAGE_B)

__device__ __forceinline__ void prefetch_chunk(
        int cNum, uint32_t sbase, int m0, int tid,
        const __nv_bfloat16* Ah, const __nv_bfloat16* Al,
        const __nv_bfloat16* AtH, const __nv_bfloat16* AtL,
        const __nv_bfloat16* Bh, const __nv_bfloat16* Bl) {
    const __nv_bfloat16 *ah, *al;
    int lda, kofs;
    if (cNum < 16) { ah = Ah;  al = Al;  lda = KB; kofs = cNum * BKC; }
    else           { ah = AtH; al = AtL; lda = FF; kofs = (cNum - 16) * BKC; }
#pragma unroll
    for (int i = 0; i < 2; i++) {
        int idx = tid + i * 256;        // 0..511
        int r = idx >> 2;               // 0..127
        int c = idx & 3;                // 16B chunk within 64B row
        uint32_t dst = sbase + r * 64 + ((c ^ ((r >> 1) & 3)) << 4);
        int gr = m0 + r;
        int sz = (gr < NN) ? 16 : 0;
        int grc = (gr < NN) ? gr : 0;
        long aofs = (long)grc * lda + kofs + c * 8;
        cp16(dst,              ah + aofs, sz);
        cp16(dst + TILE_B,     al + aofs, sz);
        long bofs = (long)r * GK + cNum * BKC + c * 8;
        cp16(dst + 2 * TILE_B, Bh + bofs, 16);
        cp16(dst + 3 * TILE_B, Bl + bofs, 16);
    }
}

__global__ void __launch_bounds__(256, 2) k_gemm_mma(
        const __nv_bfloat16* __restrict__ Ah, const __nv_bfloat16* __restrict__ Al,
        const __nv_bfloat16* __restrict__ AtH, const __nv_bfloat16* __restrict__ AtL,
        const __nv_bfloat16* __restrict__ Bh, const __nv_bfloat16* __restrict__ Bl,
        const float* __restrict__ biasc,
        float* __restrict__ out) {
    extern __shared__ float4 smem_raw[];
    uint32_t sm0 = smem_u32(smem_raw);
    const int tid = threadIdx.x;
    const int wid = tid >> 5;
    const int lane = tid & 31;
    const int m0 = blockIdx.x * 128;
    const int warp_m = (wid & 3) * 32;
    const int warp_n = (wid >> 2) * 64;
    const int g = lane >> 2;
    const int t = lane & 3;
    const int rr = lane & 7;
    const int mid = lane >> 3;

    float acc[2][8][4];
#pragma unroll
    for (int mt = 0; mt < 2; mt++)
#pragma unroll
        for (int nt = 0; nt < 8; nt++)
#pragma unroll
            for (int q = 0; q < 4; q++) acc[mt][nt][q] = 0.f;

    prefetch_chunk(0, sm0, m0, tid, Ah, Al, AtH, AtL, Bh, Bl);
    CP_COMMIT();

#pragma unroll 1
    for (int c = 0; c < NCHUNK; c++) {
        if (c + 1 < NCHUNK) {
            prefetch_chunk(c + 1, sm0 + ((c + 1) & 1) * STAGE_B, m0, tid,
                           Ah, Al, AtH, AtL, Bh, Bl);
            CP_COMMIT();
            CP_WAIT1();
        } else {
            CP_WAIT0();
        }
        __syncthreads();
        const uint32_t su = sm0 + (c & 1) * STAGE_B;
#pragma unroll
        for (int s = 0; s < 2; s++) {
            const int c0 = s * 2;
            // ---- A fragments via ldmatrix.x4 ----
            uint32_t a_h[2][4], a_l[2][4];
#pragma unroll
            for (int mt = 0; mt < 2; mt++) {
                int arow = warp_m + mt * 16 + ((mid & 1) << 3) + rr;
                int achk = c0 + (mid >> 1);
                uint32_t aaddr = su + arow * 64 + (((achk ^ ((arow >> 1) & 3))) << 4);
                LDSM4(a_h[mt], aaddr);
                LDSM4(a_l[mt], aaddr + TILE_B);
            }
            // ---- B in pairs of n-tiles via ldmatrix.x4 ----
#pragma unroll
            for (int p = 0; p < 4; p++) {
                int brow = warp_n + (p * 2 + (mid >> 1)) * 8 + rr;
                int bchk = c0 + (mid & 1);
                uint32_t baddr = su + 2 * TILE_B + brow * 64 +
                                 (((bchk ^ ((brow >> 1) & 3))) << 4);
                uint32_t bh4[4], bl4[4];
                LDSM4(bh4, baddr);
                LDSM4(bl4, baddr + TILE_B);
#pragma unroll
                for (int q = 0; q < 2; q++) {
                    const int nt = p * 2 + q;
                    uint32_t bhq[2] = {bh4[q * 2], bh4[q * 2 + 1]};
                    uint32_t blq[2] = {bl4[q * 2], bl4[q * 2 + 1]};
#pragma unroll
                    for (int mt = 0; mt < 2; mt++) {
                        MMA_BF16(acc[mt][nt], a_h[mt], bhq);
                        MMA_BF16(acc[mt][nt], a_l[mt], bhq);
                        MMA_BF16(acc[mt][nt], a_h[mt], blq);
                    }
                }
            }
        }
        __syncthreads();
    }

    // epilogue: bias + store
#pragma unroll
    for (int mt = 0; mt < 2; mt++) {
        const int r0 = m0 + warp_m + mt * 16 + g;
#pragma unroll
        for (int nt = 0; nt < 8; nt++) {
            const int col = warp_n + nt * 8 + t * 2;
            const float b0 = biasc[col];
            const float b1 = biasc[col + 1];
            if (r0 < NN) {
                float2 o = make_float2(acc[mt][nt][0] + b0, acc[mt][nt][1] + b1);
                *reinterpret_cast<float2*>(out + (long)r0 * FF + col) = o;
            }
            if (r0 + 8 < NN) {
                float2 o = make_float2(acc[mt][nt][2] + b0, acc[mt][nt][3] + b1);
                *reinterpret_cast<float2*>(out + (long)(r0 + 8) * FF + col) = o;
            }
        }
    }
}

// ---------------- BatchNorm (training stats) + ReLU ----------------
#define BN_NB 200
__global__ void k_bn_part(const float* __restrict__ x1) {
    int b = blockIdx.x;
    int t = threadIdx.x;
    int per = (NN + BN_NB - 1) / BN_NB;
    int r0 = b * per;
    int r1 = (r0 + per < NN) ? r0 + per : NN;
    float s = 0.f, q = 0.f;
    for (int r = r0; r < r1; r++) {
        float v = x1[(long)r * FF + t];
        s += v;
        q += v * v;
    }
    d_bnpart[b * FF + t] = s;
    d_bnpart[BN_NB * FF + b * FF + t] = q;
}

__global__ void k_bn_final(const float* __restrict__ gamma, const float* __restrict__ beta) {
    int t = threadIdx.x;
    float s = 0.f, q = 0.f;
    for (int b = 0; b < BN_NB; b++) {
        s += d_bnpart[b * FF + t];
        q += d_bnpart[BN_NB * FF + b * FF + t];
    }
    float mean = s / (float)NN;
    float var = q / (float)NN - mean * mean;
    float inv = rsqrtf(var + EPSV);
    float sc = gamma[t] * inv;
    d_scale[t] = sc;
    d_shift[t] = beta[t] - mean * sc;
}

__global__ void k_bn_apply(const float* __restrict__ x1) {
    long i = (long)blockIdx.x * blockDim.x + threadIdx.x;
    if (i < (long)NN * FF) {
        int c = (int)(i & (FF - 1));
        float v = fmaxf(x1[i] * d_scale[c] + d_shift[c], 0.f);
        d_xr[i] = v;
        __nv_bfloat16 h = __float2bfloat16(v);
        d_xrh[i] = h;
        d_xrl[i] = __float2bfloat16(v - __bfloat162float(h));
    }
}

// ---------------- launch ----------------
extern "C" void kernel_launch(void* const* d_in, const int* in_sizes, int n_in,
                              void* d_out, int out_size) {
    const float* x      = (const float*)d_in[0];
    const int*   ei     = (const int*)d_in[1];
    const int*   etype  = (const int*)d_in[2];
    const float* comp1  = (const float*)d_in[3];
    const float* bases1 = (const float*)d_in[4];
    const float* root1  = (const float*)d_in[5];
    const float* bias1  = (const float*)d_in[6];
    const float* skip1w = (const float*)d_in[7];
    const float* skip1b = (const float*)d_in[8];
    const float* gamma  = (const float*)d_in[9];
    const float* beta   = (const float*)d_in[10];
    const float* comp2  = (const float*)d_in[11];
    const float* bases2 = (const float*)d_in[12];
    const float* root2  = (const float*)d_in[13];
    const float* bias2  = (const float*)d_in[14];
    const float* skip2w = (const float*)d_in[15];
    const float* skip2b = (const float*)d_in[16];

    float* h_out  = (float*)d_out;                // x1 pre-BN
    float* x2_out = (float*)d_out + (long)NN * FF;

    const int* src = ei;
    const int* dst = ei + EE;

    __nv_bfloat16 *accBh, *accBl, *xh, *xl, *xrh, *xrl;
    __nv_bfloat16 *Wh1, *Wl1, *Wh2, *Wl2;
    float *xr, *bc1, *bc2;
    cudaGetSymbolAddress((void**)&accBh, d_accBh);
    cudaGetSymbolAddress((void**)&accBl, d_accBl);
    cudaGetSymbolAddress((void**)&xh, d_xh);
    cudaGetSymbolAddress((void**)&xl, d_xl);
    cudaGetSymbolAddress((void**)&xrh, d_xrh);
    cudaGetSymbolAddress((void**)&xrl, d_xrl);
    cudaGetSymbolAddress((void**)&xr, d_xr);
    cudaGetSymbolAddress((void**)&Wh1, d_Wbh1);
    cudaGetSymbolAddress((void**)&Wl1, d_Wbl1);
    cudaGetSymbolAddress((void**)&Wh2, d_Wbh2);
    cudaGetSymbolAddress((void**)&Wl2, d_Wbl2);
    cudaGetSymbolAddress((void**)&bc1, d_biasc1);
    cudaGetSymbolAddress((void**)&bc2, d_biasc2);

    static bool attr_done = false;
    if (!attr_done) {
        cudaFuncSetAttribute(k_gemm_mma, cudaFuncAttributeMaxDynamicSharedMemorySize, GEMM_SMEM);
        attr_done = true;
    }

    const int EB = (EE + 255) / 256;
    const int NB = (NN * FF + 255) / 256;
    const int GEMM_GRID = (NN + 127) / 128;

    // ---- weight prep + input split (independent of graph) ----
    k_split_x<<<NB, 256>>>(x);
    k_prep<<<GK, FF>>>(root1, skip1w, bias1, skip1b, bases1, Wh1, Wl1, bc1);
    k_prep<<<GK, FF>>>(root2, skip2w, bias2, skip2b, bases2, Wh2, Wl2, bc2);

    // ---- CSR build (shared by both layers) ----
    k_zero_meta<<<1600, 256>>>();
    k_count<<<EB, 256>>>(dst, etype);
    k_scan_local<<<SCAN_NB, SCAN_CHUNK>>>();
    k_scan_chunks<<<1, 32>>>();
    k_scan_add<<<SCAN_NB, SCAN_CHUNK>>>();
    k_scatter<<<EB, 256>>>(src, dst, etype);

    // ---- layer 1 ----
    k_agg<<<NN, 128>>>(x, comp1);
    k_gemm_mma<<<GEMM_GRID, 256, GEMM_SMEM>>>(accBh, accBl, xh, xl, Wh1, Wl1, bc1, h_out);

    // ---- BN + ReLU ----
    k_bn_part<<<BN_NB, FF>>>(h_out);
    k_bn_final<<<1, FF>>>(gamma, beta);
    k_bn_apply<<<NB, 256>>>(h_out);

    // ---- layer 2 ----
    k_agg<<<NN, 128>>>(xr, comp2);
    k_gemm_mma<<<GEMM_GRID, 256, GEMM_SMEM>>>(accBh, accBl, xrh, xrl, Wh2, Wl2, bc2, x2_out);
}

// round 10
// speedup vs baseline: 2.7335x; 1.1291x over previous
#include <cuda_runtime.h>
#include <cuda_fp16.h>
#include <cstdint>

// ---------------- problem constants ----------------
#define NN   50000
#define EE   800000
#define RR   8
#define BB   4
#define FF   128            // in = hidden = 128
#define KB   (BB*FF)        // 512, basis-contracted K
#define GK   640            // total GEMM K = 512 (accB) + 128 (x)
#define EPSV 1e-5f

// ---------------- scratch (static device globals; no allocs) ----------------
__device__ __half d_accBh[NN * KB];   // aggregated messages, fp16 hi
__device__ __half d_accBl[NN * KB];   // fp16 lo residual
__device__ __half d_xh[NN * FF];      // split of layer-1 input x
__device__ __half d_xl[NN * FF];
__device__ __half d_xrh[NN * FF];     // split of relu(bn(x1))
__device__ __half d_xrl[NN * FF];
__device__ float d_xr[NN * FF];       // fp32 relu(bn(x1)) for aggregation
__device__ __half d_Wb1[FF * GK];     // layer-1 weight, [n][k], fp16
__device__ __half d_Wb2[FF * GK];     // layer-2 weight
__device__ float d_biasc1[FF];
__device__ float d_biasc2[FF];
__device__ int   d_off[NN + 1];
__device__ int   d_cursor[NN];
__device__ int   d_cnt[NN * RR];
__device__ int   d_esort[EE];         // packed (etype<<20)|src
__device__ int   d_chunksum[64];
__device__ float d_bnpart[2 * 200 * FF];
__device__ float d_scale[FF];
__device__ float d_shift[FF];

// ---------------- helpers ----------------
__device__ __forceinline__ uint32_t smem_u32(const void* p) {
    uint32_t a;
    asm("{ .reg .u64 t; cvta.to.shared.u64 t, %1; cvt.u32.u64 %0, t; }" : "=r"(a) : "l"(p));
    return a;
}
__device__ __forceinline__ void cp16(uint32_t dst, const void* src, int szbytes) {
    asm volatile("cp.async.cg.shared.global [%0], [%1], 16, %2;"
                 :: "r"(dst), "l"(src), "r"(szbytes) : "memory");
}
#define CP_COMMIT() asm volatile("cp.async.commit_group;" ::: "memory")
#define CP_WAIT1()  asm volatile("cp.async.wait_group 1;" ::: "memory")
#define CP_WAIT0()  asm volatile("cp.async.wait_group 0;" ::: "memory")

#define LDSM4(R, addr)                                                        \
    asm volatile("ldmatrix.sync.aligned.m8n8.x4.shared.b16 {%0,%1,%2,%3}, [%4];" \
                 : "=r"((R)[0]), "=r"((R)[1]), "=r"((R)[2]), "=r"((R)[3])     \
                 : "r"(addr))

#define MMA_F16(acc, a, b)                                                    \
    asm volatile(                                                             \
        "mma.sync.aligned.m16n8k16.row.col.f32.f16.f16.f32 "                  \
        "{%0,%1,%2,%3}, {%4,%5,%6,%7}, {%8,%9}, {%0,%1,%2,%3};"               \
        : "+f"((acc)[0]), "+f"((acc)[1]), "+f"((acc)[2]), "+f"((acc)[3])      \
        : "r"((a)[0]), "r"((a)[1]), "r"((a)[2]), "r"((a)[3]),                 \
          "r"((b)[0]), "r"((b)[1]))

// ---------------- CSR build ----------------
__global__ void k_zero_meta() {
    int i = blockIdx.x * blockDim.x + threadIdx.x;
    int stride = gridDim.x * blockDim.x;
    for (int j = i; j < NN; j += stride) d_cursor[j] = 0;
    for (int j = i; j < NN * RR; j += stride) d_cnt[j] = 0;
}

__global__ void k_count(const int* __restrict__ dst, const int* __restrict__ et) {
    int e = blockIdx.x * blockDim.x + threadIdx.x;
    if (e < EE) atomicAdd(&d_cnt[dst[e] * RR + et[e]], 1);
}

#define SCAN_CHUNK 1024
#define SCAN_NB    49

__global__ void k_scan_local() {
    __shared__ int sh[SCAN_CHUNK];
    int i = blockIdx.x * SCAN_CHUNK + threadIdx.x;
    int v = 0;
    if (i < NN) {
#pragma unroll
        for (int r = 0; r < RR; r++) v += d_cnt[i * RR + r];
    }
    sh[threadIdx.x] = v;
    __syncthreads();
    for (int s = 1; s < SCAN_CHUNK; s <<= 1) {
        int t = (threadIdx.x >= s) ? sh[threadIdx.x - s] : 0;
        __syncthreads();
        sh[threadIdx.x] += t;
        __syncthreads();
    }
    if (i < NN) d_off[i] = sh[threadIdx.x] - v;
    if (threadIdx.x == SCAN_CHUNK - 1) d_chunksum[blockIdx.x] = sh[threadIdx.x];
}

__global__ void k_scan_chunks() {
    if (threadIdx.x == 0 && blockIdx.x == 0) {
        int acc = 0;
        for (int b = 0; b < SCAN_NB; b++) { int t = d_chunksum[b]; d_chunksum[b] = acc; acc += t; }
    }
}

__global__ void k_scan_add() {
    int i = blockIdx.x * SCAN_CHUNK + threadIdx.x;
    if (i < NN) d_off[i] += d_chunksum[blockIdx.x];
    if (i == 0) d_off[NN] = EE;
}

__global__ void k_scatter(const int* __restrict__ src, const int* __restrict__ dst,
                          const int* __restrict__ et) {
    int e = blockIdx.x * blockDim.x + threadIdx.x;
    if (e < EE) {
        int d = dst[e];
        int pos = d_off[d] + atomicAdd(&d_cursor[d], 1);
        d_esort[pos] = (et[e] << 20) | src[e];
    }
}

// ---------------- per-layer weight prep: [n][k] fp16 ----------------
__global__ void k_prep(const float* __restrict__ root, const float* __restrict__ skipw,
                       const float* __restrict__ bias, const float* __restrict__ skipb,
                       const float* __restrict__ bases,
                       __half* __restrict__ Wh, float* __restrict__ biasc) {
    int k = blockIdx.x;
    int n = threadIdx.x;
    float w = (k < KB) ? bases[k * FF + n]
                       : root[(k - KB) * FF + n] + skipw[(k - KB) * FF + n];
    Wh[n * GK + k] = __float2half(w);
    if (k == 0) biasc[n] = bias[n] + skipb[n];
}

// ---------------- split fp32 -> fp16 hi/lo ----------------
__global__ void k_split_x(const float* __restrict__ x) {
    long i = (long)blockIdx.x * blockDim.x + threadIdx.x;
    if (i < (long)NN * FF) {
        float v = x[i];
        __half h = __float2half(v);
        d_xh[i] = h;
        d_xl[i] = __float2half(v - __half2float(h));
    }
}

// ---------------- aggregation: one block (128 thr) per node ----------------
__global__ void __launch_bounds__(128) k_agg(const float* __restrict__ xin,
                                             const float* __restrict__ comp) {
    __shared__ float sc[RR * BB];
    int node = blockIdx.x;
    int t = threadIdx.x;
    if (t < RR * BB) {
        int r = t >> 2;
        float c = (float)d_cnt[node * RR + r];
        sc[t] = comp[t] / fmaxf(c, 1.0f);
    }
    __syncthreads();
    int s = d_off[node], e = d_off[node + 1];
    float a0 = 0.f, a1 = 0.f, a2 = 0.f, a3 = 0.f;
    int i = s;
    for (; i + 4 <= e; i += 4) {
        int p0 = d_esort[i + 0], p1 = d_esort[i + 1];
        int p2 = d_esort[i + 2], p3 = d_esort[i + 3];
        int r0 = p0 >> 20, r1 = p1 >> 20, r2 = p2 >> 20, r3 = p3 >> 20;
        float v0 = xin[(p0 & 0xFFFFF) * FF + t];
        float v1 = xin[(p1 & 0xFFFFF) * FF + t];
        float v2 = xin[(p2 & 0xFFFFF) * FF + t];
        float v3 = xin[(p3 & 0xFFFFF) * FF + t];
        a0 += v0 * sc[r0 * 4 + 0] + v1 * sc[r1 * 4 + 0] + v2 * sc[r2 * 4 + 0] + v3 * sc[r3 * 4 + 0];
        a1 += v0 * sc[r0 * 4 + 1] + v1 * sc[r1 * 4 + 1] + v2 * sc[r2 * 4 + 1] + v3 * sc[r3 * 4 + 1];
        a2 += v0 * sc[r0 * 4 + 2] + v1 * sc[r1 * 4 + 2] + v2 * sc[r2 * 4 + 2] + v3 * sc[r3 * 4 + 2];
        a3 += v0 * sc[r0 * 4 + 3] + v1 * sc[r1 * 4 + 3] + v2 * sc[r2 * 4 + 3] + v3 * sc[r3 * 4 + 3];
    }
    for (; i < e; i++) {
        int p = d_esort[i];
        int r = p >> 20;
        float v = xin[(p & 0xFFFFF) * FF + t];
        a0 += v * sc[r * 4 + 0];
        a1 += v * sc[r * 4 + 1];
        a2 += v * sc[r * 4 + 2];
        a3 += v * sc[r * 4 + 3];
    }
    float vals[4] = {a0, a1, a2, a3};
    long base = (long)node * KB + t;
#pragma unroll
    for (int b = 0; b < 4; b++) {
        __half h = __float2half(vals[b]);
        d_accBh[base + b * FF] = h;
        d_accBl[base + b * FF] = __float2half(vals[b] - __half2float(h));
    }
}

// ---------------- mma.sync fp16 GEMM, 2-term split + ldmatrix ----------------
// out[m][n] = sum_k (Ah+Al)[m][k]*W[k][n] + biasc[n];  A = [accB | x], K = 640
// CTA tile 128x128, BK=32, 8 warps (4 M x 2 N), warp tile 32x64, 2 CTAs/SM.
// SMEM per stage: Ah, Al, Bh tiles of 128x32 fp16 (8KB each) = 24KB; 2 stages.
// Swizzle: 64B rows; 16B slot = (chunk ^ ((row>>1)&3)).
#define BKC     32
#define NCHUNK  20
#define TILE_B  8192
#define STAGE_B 24576
#define GEMM_SMEM (2 * STAGE_B)

__device__ __forceinline__ void prefetch_chunk(
        int cNum, uint32_t sbase, int m0, int tid,
        const __half* Ah, const __half* Al,
        const __half* AtH, const __half* AtL,
        const __half* Bh) {
    const __half *ah, *al;
    int lda, kofs;
    if (cNum < 16) { ah = Ah;  al = Al;  lda = KB; kofs = cNum * BKC; }
    else           { ah = AtH; al = AtL; lda = FF; kofs = (cNum - 16) * BKC; }
#pragma unroll
    for (int i = 0; i < 2; i++) {
        int idx = tid + i * 256;        // 0..511
        int r = idx >> 2;               // 0..127
        int c = idx & 3;                // 16B chunk within 64B row
        uint32_t dst = sbase + r * 64 + ((c ^ ((r >> 1) & 3)) << 4);
        int gr = m0 + r;
        int sz = (gr < NN) ? 16 : 0;
        int grc = (gr < NN) ? gr : 0;
        long aofs = (long)grc * lda + kofs + c * 8;
        cp16(dst,              ah + aofs, sz);
        cp16(dst + TILE_B,     al + aofs, sz);
        long bofs = (long)r * GK + cNum * BKC + c * 8;
        cp16(dst + 2 * TILE_B, Bh + bofs, 16);
    }
}

__global__ void __launch_bounds__(256, 2) k_gemm_mma(
        const __half* __restrict__ Ah, const __half* __restrict__ Al,
        const __half* __restrict__ AtH, const __half* __restrict__ AtL,
        const __half* __restrict__ Bh,
        const float* __restrict__ biasc,
        float* __restrict__ out) {
    extern __shared__ float4 smem_raw[];
    uint32_t sm0 = smem_u32(smem_raw);
    const int tid = threadIdx.x;
    const int wid = tid >> 5;
    const int lane = tid & 31;
    const int m0 = blockIdx.x * 128;
    const int warp_m = (wid & 3) * 32;
    const int warp_n = (wid >> 2) * 64;
    const int g = lane >> 2;
    const int t = lane & 3;
    const int rr = lane & 7;
    const int mid = lane >> 3;

    float acc[2][8][4];
#pragma unroll
    for (int mt = 0; mt < 2; mt++)
#pragma unroll
        for (int nt = 0; nt < 8; nt++)
#pragma unroll
            for (int q = 0; q < 4; q++) acc[mt][nt][q] = 0.f;

    prefetch_chunk(0, sm0, m0, tid, Ah, Al, AtH, AtL, Bh);
    CP_COMMIT();

#pragma unroll 1
    for (int c = 0; c < NCHUNK; c++) {
        if (c + 1 < NCHUNK) {
            prefetch_chunk(c + 1, sm0 + ((c + 1) & 1) * STAGE_B, m0, tid,
                           Ah, Al, AtH, AtL, Bh);
            CP_COMMIT();
            CP_WAIT1();
        } else {
            CP_WAIT0();
        }
        __syncthreads();
        const uint32_t su = sm0 + (c & 1) * STAGE_B;
#pragma unroll
        for (int s = 0; s < 2; s++) {
            const int c0 = s * 2;
            // ---- A fragments via ldmatrix.x4 ----
            uint32_t a_h[2][4], a_l[2][4];
#pragma unroll
            for (int mt = 0; mt < 2; mt++) {
                int arow = warp_m + mt * 16 + ((mid & 1) << 3) + rr;
                int achk = c0 + (mid >> 1);
                uint32_t aaddr = su + arow * 64 + (((achk ^ ((arow >> 1) & 3))) << 4);
                LDSM4(a_h[mt], aaddr);
                LDSM4(a_l[mt], aaddr + TILE_B);
            }
            // ---- B in pairs of n-tiles via ldmatrix.x4 ----
#pragma unroll
            for (int p = 0; p < 4; p++) {
                int brow = warp_n + (p * 2 + (mid >> 1)) * 8 + rr;
                int bchk = c0 + (mid & 1);
                uint32_t baddr = su + 2 * TILE_B + brow * 64 +
                                 (((bchk ^ ((brow >> 1) & 3))) << 4);
                uint32_t bh4[4];
                LDSM4(bh4, baddr);
#pragma unroll
                for (int q = 0; q < 2; q++) {
                    const int nt = p * 2 + q;
                    uint32_t bhq[2] = {bh4[q * 2], bh4[q * 2 + 1]};
#pragma unroll
                    for (int mt = 0; mt < 2; mt++) {
                        MMA_F16(acc[mt][nt], a_h[mt], bhq);
                        MMA_F16(acc[mt][nt], a_l[mt], bhq);
                    }
                }
            }
        }
        __syncthreads();
    }

    // epilogue: bias + store
#pragma unroll
    for (int mt = 0; mt < 2; mt++) {
        const int r0 = m0 + warp_m + mt * 16 + g;
#pragma unroll
        for (int nt = 0; nt < 8; nt++) {
            const int col = warp_n + nt * 8 + t * 2;
            const float b0 = biasc[col];
            const float b1 = biasc[col + 1];
            if (r0 < NN) {
                float2 o = make_float2(acc[mt][nt][0] + b0, acc[mt][nt][1] + b1);
                *reinterpret_cast<float2*>(out + (long)r0 * FF + col) = o;
            }
            if (r0 + 8 < NN) {
                float2 o = make_float2(acc[mt][nt][2] + b0, acc[mt][nt][3] + b1);
                *reinterpret_cast<float2*>(out + (long)(r0 + 8) * FF + col) = o;
            }
        }
    }
}

// ---------------- BatchNorm (training stats) + ReLU ----------------
#define BN_NB 200
__global__ void k_bn_part(const float* __restrict__ x1) {
    int b = blockIdx.x;
    int t = threadIdx.x;
    int per = (NN + BN_NB - 1) / BN_NB;
    int r0 = b * per;
    int r1 = (r0 + per < NN) ? r0 + per : NN;
    float s = 0.f, q = 0.f;
    for (int r = r0; r < r1; r++) {
        float v = x1[(long)r * FF + t];
        s += v;
        q += v * v;
    }
    d_bnpart[b * FF + t] = s;
    d_bnpart[BN_NB * FF + b * FF + t] = q;
}

__global__ void k_bn_final(const float* __restrict__ gamma, const float* __restrict__ beta) {
    int t = threadIdx.x;
    float s = 0.f, q = 0.f;
    for (int b = 0; b < BN_NB; b++) {
        s += d_bnpart[b * FF + t];
        q += d_bnpart[BN_NB * FF + b * FF + t];
    }
    float mean = s / (float)NN;
    float var = q / (float)NN - mean * mean;
    float inv = rsqrtf(var + EPSV);
    float sc = gamma[t] * inv;
    d_scale[t] = sc;
    d_shift[t] = beta[t] - mean * sc;
}

__global__ void k_bn_apply(const float* __restrict__ x1) {
    long i = (long)blockIdx.x * blockDim.x + threadIdx.x;
    if (i < (long)NN * FF) {
        int c = (int)(i & (FF - 1));
        float v = fmaxf(x1[i] * d_scale[c] + d_shift[c], 0.f);
        d_xr[i] = v;
        __half h = __float2half(v);
        d_xrh[i] = h;
        d_xrl[i] = __float2half(v - __half2float(h));
    }
}

// ---------------- launch ----------------
extern "C" void kernel_launch(void* const* d_in, const int* in_sizes, int n_in,
                              void* d_out, int out_size) {
    const float* x      = (const float*)d_in[0];
    const int*   ei     = (const int*)d_in[1];
    const int*   etype  = (const int*)d_in[2];
    const float* comp1  = (const float*)d_in[3];
    const float* bases1 = (const float*)d_in[4];
    const float* root1  = (const float*)d_in[5];
    const float* bias1  = (const float*)d_in[6];
    const float* skip1w = (const float*)d_in[7];
    const float* skip1b = (const float*)d_in[8];
    const float* gamma  = (const float*)d_in[9];
    const float* beta   = (const float*)d_in[10];
    const float* comp2  = (const float*)d_in[11];
    const float* bases2 = (const float*)d_in[12];
    const float* root2  = (const float*)d_in[13];
    const float* bias2  = (const float*)d_in[14];
    const float* skip2w = (const float*)d_in[15];
    const float* skip2b = (const float*)d_in[16];

    float* h_out  = (float*)d_out;                // x1 pre-BN
    float* x2_out = (float*)d_out + (long)NN * FF;

    const int* src = ei;
    const int* dst = ei + EE;

    __half *accBh, *accBl, *xh, *xl, *xrh, *xrl;
    __half *W1, *W2;
    float *xr, *bc1, *bc2;
    cudaGetSymbolAddress((void**)&accBh, d_accBh);
    cudaGetSymbolAddress((void**)&accBl, d_accBl);
    cudaGetSymbolAddress((void**)&xh, d_xh);
    cudaGetSymbolAddress((void**)&xl, d_xl);
    cudaGetSymbolAddress((void**)&xrh, d_xrh);
    cudaGetSymbolAddress((void**)&xrl, d_xrl);
    cudaGetSymbolAddress((void**)&xr, d_xr);
    cudaGetSymbolAddress((void**)&W1, d_Wb1);
    cudaGetSymbolAddress((void**)&W2, d_Wb2);
    cudaGetSymbolAddress((void**)&bc1, d_biasc1);
    cudaGetSymbolAddress((void**)&bc2, d_biasc2);

    static bool attr_done = false;
    if (!attr_done) {
        cudaFuncSetAttribute(k_gemm_mma, cudaFuncAttributeMaxDynamicSharedMemorySize, GEMM_SMEM);
        attr_done = true;
    }

    const int EB = (EE + 255) / 256;
    const int NB = (NN * FF + 255) / 256;
    const int GEMM_GRID = (NN + 127) / 128;

    // ---- weight prep + input split (independent of graph) ----
    k_split_x<<<NB, 256>>>(x);
    k_prep<<<GK, FF>>>(root1, skip1w, bias1, skip1b, bases1, W1, bc1);
    k_prep<<<GK, FF>>>(root2, skip2w, bias2, skip2b, bases2, W2, bc2);

    // ---- CSR build (shared by both layers) ----
    k_zero_meta<<<1600, 256>>>();
    k_count<<<EB, 256>>>(dst, etype);
    k_scan_local<<<SCAN_NB, SCAN_CHUNK>>>();
    k_scan_chunks<<<1, 32>>>();
    k_scan_add<<<SCAN_NB, SCAN_CHUNK>>>();
    k_scatter<<<EB, 256>>>(src, dst, etype);

    // ---- layer 1 ----
    k_agg<<<NN, 128>>>(x, comp1);
    k_gemm_mma<<<GEMM_GRID, 256, GEMM_SMEM>>>(accBh, accBl, xh, xl, W1, bc1, h_out);

    // ---- BN + ReLU ----
    k_bn_part<<<BN_NB, FF>>>(h_out);
    k_bn_final<<<1, FF>>>(gamma, beta);
    k_bn_apply<<<NB, 256>>>(h_out);

    // ---- layer 2 ----
    k_agg<<<NN, 128>>>(xr, comp2);
    k_gemm_mma<<<GEMM_GRID, 256, GEMM_SMEM>>>(accBh, accBl, xrh, xrl, W2, bc2, x2_out);
}

// round 12
// speedup vs baseline: 3.1512x; 1.1528x over previous
#include <cuda_runtime.h>
#include <cuda_fp16.h>
#include <cstdint>

// ---------------- problem constants ----------------
#define NN   50000
#define EE   800000
#define RR   8
#define BB   4
#define FF   128            // in = hidden = 128
#define KB   (BB*FF)        // 512, basis-contracted K
#define GK   640            // total GEMM K = 512 (accB) + 128 (x)
#define EPSV 1e-5f

// ---------------- scratch (static device globals; no allocs) ----------------
__device__ __half d_accB[NN * KB];    // aggregated messages, fp16
__device__ __half d_xh[NN * FF];      // fp16 of layer-1 input x
__device__ __half d_xrh[NN * FF];     // fp16 of relu(bn(x1))
__device__ float d_xr[NN * FF];       // fp32 relu(bn(x1)) for aggregation
__device__ __half d_Wb1[FF * GK];     // layer-1 weight, [n][k], fp16
__device__ __half d_Wb2[FF * GK];     // layer-2 weight
__device__ float d_biasc1[FF];
__device__ float d_biasc2[FF];
__device__ int   d_off[NN + 1];
__device__ int   d_cursor[NN];
__device__ int   d_cnt[NN * RR];
__device__ int   d_esort[EE];         // packed (etype<<20)|src
__device__ int   d_chunksum[64];
__device__ float d_bnpart[2 * 200 * FF];
__device__ float d_scale[FF];
__device__ float d_shift[FF];

// ---------------- helpers ----------------
__device__ __forceinline__ uint32_t smem_u32(const void* p) {
    uint32_t a;
    asm("{ .reg .u64 t; cvta.to.shared.u64 t, %1; cvt.u32.u64 %0, t; }" : "=r"(a) : "l"(p));
    return a;
}
__device__ __forceinline__ void cp16(uint32_t dst, const void* src, int szbytes) {
    asm volatile("cp.async.cg.shared.global [%0], [%1], 16, %2;"
                 :: "r"(dst), "l"(src), "r"(szbytes) : "memory");
}
#define CP_COMMIT() asm volatile("cp.async.commit_group;" ::: "memory")
#define CP_WAIT1()  asm volatile("cp.async.wait_group 1;" ::: "memory")
#define CP_WAIT0()  asm volatile("cp.async.wait_group 0;" ::: "memory")

#define LDSM4(R, addr)                                                        \
    asm volatile("ldmatrix.sync.aligned.m8n8.x4.shared.b16 {%0,%1,%2,%3}, [%4];" \
                 : "=r"((R)[0]), "=r"((R)[1]), "=r"((R)[2]), "=r"((R)[3])     \
                 : "r"(addr))

#define MMA_F16(acc, a, b)                                                    \
    asm volatile(                                                             \
        "mma.sync.aligned.m16n8k16.row.col.f32.f16.f16.f32 "                  \
        "{%0,%1,%2,%3}, {%4,%5,%6,%7}, {%8,%9}, {%0,%1,%2,%3};"               \
        : "+f"((acc)[0]), "+f"((acc)[1]), "+f"((acc)[2]), "+f"((acc)[3])      \
        : "r"((a)[0]), "r"((a)[1]), "r"((a)[2]), "r"((a)[3]),                 \
          "r"((b)[0]), "r"((b)[1]))

// ---------------- CSR build ----------------
__global__ void k_zero_meta() {
    int i = blockIdx.x * blockDim.x + threadIdx.x;
    int stride = gridDim.x * blockDim.x;
    for (int j = i; j < NN; j += stride) d_cursor[j] = 0;
    for (int j = i; j < NN * RR; j += stride) d_cnt[j] = 0;
}

__global__ void k_count(const int* __restrict__ dst, const int* __restrict__ et) {
    int e = blockIdx.x * blockDim.x + threadIdx.x;
    if (e < EE) atomicAdd(&d_cnt[dst[e] * RR + et[e]], 1);
}

#define SCAN_CHUNK 1024
#define SCAN_NB    49

__global__ void k_scan_local() {
    __shared__ int sh[SCAN_CHUNK];
    int i = blockIdx.x * SCAN_CHUNK + threadIdx.x;
    int v = 0;
    if (i < NN) {
#pragma unroll
        for (int r = 0; r < RR; r++) v += d_cnt[i * RR + r];
    }
    sh[threadIdx.x] = v;
    __syncthreads();
    for (int s = 1; s < SCAN_CHUNK; s <<= 1) {
        int t = (threadIdx.x >= s) ? sh[threadIdx.x - s] : 0;
        __syncthreads();
        sh[threadIdx.x] += t;
        __syncthreads();
    }
    if (i < NN) d_off[i] = sh[threadIdx.x] - v;
    if (threadIdx.x == SCAN_CHUNK - 1) d_chunksum[blockIdx.x] = sh[threadIdx.x];
}

__global__ void k_scan_chunks() {
    if (threadIdx.x == 0 && blockIdx.x == 0) {
        int acc = 0;
        for (int b = 0; b < SCAN_NB; b++) { int t = d_chunksum[b]; d_chunksum[b] = acc; acc += t; }
    }
}

__global__ void k_scan_add() {
    int i = blockIdx.x * SCAN_CHUNK + threadIdx.x;
    if (i < NN) d_off[i] += d_chunksum[blockIdx.x];
    if (i == 0) d_off[NN] = EE;
}

__global__ void k_scatter(const int* __restrict__ src, const int* __restrict__ dst,
                          const int* __restrict__ et) {
    int e = blockIdx.x * blockDim.x + threadIdx.x;
    if (e < EE) {
        int d = dst[e];
        int pos = d_off[d] + atomicAdd(&d_cursor[d], 1);
        d_esort[pos] = (et[e] << 20) | src[e];
    }
}

// ---------------- per-layer weight prep: [n][k] fp16 ----------------
__global__ void k_prep(const float* __restrict__ root, const float* __restrict__ skipw,
                       const float* __restrict__ bias, const float* __restrict__ skipb,
                       const float* __restrict__ bases,
                       __half* __restrict__ Wh, float* __restrict__ biasc) {
    int k = blockIdx.x;
    int n = threadIdx.x;
    float w = (k < KB) ? bases[k * FF + n]
                       : root[(k - KB) * FF + n] + skipw[(k - KB) * FF + n];
    Wh[n * GK + k] = __float2half(w);
    if (k == 0) biasc[n] = bias[n] + skipb[n];
}

// ---------------- fp32 -> fp16 ----------------
__global__ void k_split_x(const float* __restrict__ x) {
    long i = (long)blockIdx.x * blockDim.x + threadIdx.x;
    if (i < (long)NN * FF) d_xh[i] = __float2half(x[i]);
}

// ---------------- aggregation: one block (128 thr) per node ----------------
__global__ void __launch_bounds__(128) k_agg(const float* __restrict__ xin,
                                             const float* __restrict__ comp) {
    __shared__ float sc[RR * BB];
    int node = blockIdx.x;
    int t = threadIdx.x;
    if (t < RR * BB) {
        int r = t >> 2;
        float c = (float)d_cnt[node * RR + r];
        sc[t] = comp[t] / fmaxf(c, 1.0f);
    }
    __syncthreads();
    int s = d_off[node], e = d_off[node + 1];
    float a0 = 0.f, a1 = 0.f, a2 = 0.f, a3 = 0.f;
    int i = s;
    for (; i + 4 <= e; i += 4) {
        int p0 = d_esort[i + 0], p1 = d_esort[i + 1];
        int p2 = d_esort[i + 2], p3 = d_esort[i + 3];
        int r0 = p0 >> 20, r1 = p1 >> 20, r2 = p2 >> 20, r3 = p3 >> 20;
        float v0 = xin[(p0 & 0xFFFFF) * FF + t];
        float v1 = xin[(p1 & 0xFFFFF) * FF + t];
        float v2 = xin[(p2 & 0xFFFFF) * FF + t];
        float v3 = xin[(p3 & 0xFFFFF) * FF + t];
        a0 += v0 * sc[r0 * 4 + 0] + v1 * sc[r1 * 4 + 0] + v2 * sc[r2 * 4 + 0] + v3 * sc[r3 * 4 + 0];
        a1 += v0 * sc[r0 * 4 + 1] + v1 * sc[r1 * 4 + 1] + v2 * sc[r2 * 4 + 1] + v3 * sc[r3 * 4 + 1];
        a2 += v0 * sc[r0 * 4 + 2] + v1 * sc[r1 * 4 + 2] + v2 * sc[r2 * 4 + 2] + v3 * sc[r3 * 4 + 2];
        a3 += v0 * sc[r0 * 4 + 3] + v1 * sc[r1 * 4 + 3] + v2 * sc[r2 * 4 + 3] + v3 * sc[r3 * 4 + 3];
    }
    for (; i < e; i++) {
        int p = d_esort[i];
        int r = p >> 20;
        float v = xin[(p & 0xFFFFF) * FF + t];
        a0 += v * sc[r * 4 + 0];
        a1 += v * sc[r * 4 + 1];
        a2 += v * sc[r * 4 + 2];
        a3 += v * sc[r * 4 + 3];
    }
    long base = (long)node * KB + t;
    d_accB[base + 0 * FF] = __float2half(a0);
    d_accB[base + 1 * FF] = __float2half(a1);
    d_accB[base + 2 * FF] = __float2half(a2);
    d_accB[base + 3 * FF] = __float2half(a3);
}

// ---------------- mma.sync fp16 GEMM (single term) + ldmatrix ----------------
// out[m][n] = sum_k A[m][k]*W[k][n] + biasc[n];  A = [accB | x], K = 640
// CTA tile 128x128, BK=32, 8 warps (4 M x 2 N), warp tile 32x64, 2 CTAs/SM.
// SMEM per stage: A, B tiles of 128x32 fp16 (8KB each) = 16KB; 2 stages.
// Swizzle: 64B rows; 16B slot = (chunk ^ ((row>>1)&3)).
#define BKC     32
#define NCHUNK  20
#define TILE_B  8192
#define STAGE_B 16384
#define GEMM_SMEM (2 * STAGE_B)

__device__ __forceinline__ void prefetch_chunk(
        int cNum, uint32_t sbase, int m0, int tid,
        const __half* Ah, const __half* AtH, const __half* Bh) {
    const __half* ah;
    int lda, kofs;
    if (cNum < 16) { ah = Ah;  lda = KB; kofs = cNum * BKC; }
    else           { ah = AtH; lda = FF; kofs = (cNum - 16) * BKC; }
#pragma unroll
    for (int i = 0; i < 2; i++) {
        int idx = tid + i * 256;        // 0..511
        int r = idx >> 2;               // 0..127
        int c = idx & 3;                // 16B chunk within 64B row
        uint32_t dst = sbase + r * 64 + ((c ^ ((r >> 1) & 3)) << 4);
        int gr = m0 + r;
        int sz = (gr < NN) ? 16 : 0;
        int grc = (gr < NN) ? gr : 0;
        long aofs = (long)grc * lda + kofs + c * 8;
        cp16(dst, ah + aofs, sz);
        long bofs = (long)r * GK + cNum * BKC + c * 8;
        cp16(dst + TILE_B, Bh + bofs, 16);
    }
}

__global__ void __launch_bounds__(256, 2) k_gemm_mma(
        const __half* __restrict__ Ah, const __half* __restrict__ AtH,
        const __half* __restrict__ Bh,
        const float* __restrict__ biasc,
        float* __restrict__ out) {
    extern __shared__ float4 smem_raw[];
    uint32_t sm0 = smem_u32(smem_raw);
    const int tid = threadIdx.x;
    const int wid = tid >> 5;
    const int lane = tid & 31;
    const int m0 = blockIdx.x * 128;
    const int warp_m = (wid & 3) * 32;
    const int warp_n = (wid >> 2) * 64;
    const int g = lane >> 2;
    const int t = lane & 3;
    const int rr = lane & 7;
    const int mid = lane >> 3;

    float acc[2][8][4];
#pragma unroll
    for (int mt = 0; mt < 2; mt++)
#pragma unroll
        for (int nt = 0; nt < 8; nt++)
#pragma unroll
            for (int q = 0; q < 4; q++) acc[mt][nt][q] = 0.f;

    prefetch_chunk(0, sm0, m0, tid, Ah, AtH, Bh);
    CP_COMMIT();

#pragma unroll 1
    for (int c = 0; c < NCHUNK; c++) {
        if (c + 1 < NCHUNK) {
            prefetch_chunk(c + 1, sm0 + ((c + 1) & 1) * STAGE_B, m0, tid, Ah, AtH, Bh);
            CP_COMMIT();
            CP_WAIT1();
        } else {
            CP_WAIT0();
        }
        __syncthreads();
        const uint32_t su = sm0 + (c & 1) * STAGE_B;
#pragma unroll
        for (int s = 0; s < 2; s++) {
            const int c0 = s * 2;
            // ---- A fragments via ldmatrix.x4 ----
            uint32_t a_h[2][4];
#pragma unroll
            for (int mt = 0; mt < 2; mt++) {
                int arow = warp_m + mt * 16 + ((mid & 1) << 3) + rr;
                int achk = c0 + (mid >> 1);
                uint32_t aaddr = su + arow * 64 + (((achk ^ ((arow >> 1) & 3))) << 4);
                LDSM4(a_h[mt], aaddr);
            }
            // ---- B in pairs of n-tiles via ldmatrix.x4 ----
#pragma unroll
            for (int p = 0; p < 4; p++) {
                int brow = warp_n + (p * 2 + (mid >> 1)) * 8 + rr;
                int bchk = c0 + (mid & 1);
                uint32_t baddr = su + TILE_B + brow * 64 +
                                 (((bchk ^ ((brow >> 1) & 3))) << 4);
                uint32_t bh4[4];
                LDSM4(bh4, baddr);
#pragma unroll
                for (int q = 0; q < 2; q++) {
                    const int nt = p * 2 + q;
                    uint32_t bhq[2] = {bh4[q * 2], bh4[q * 2 + 1]};
#pragma unroll
                    for (int mt = 0; mt < 2; mt++) {
                        MMA_F16(acc[mt][nt], a_h[mt], bhq);
                    }
                }
            }
        }
        __syncthreads();
    }

    // epilogue: bias + store
#pragma unroll
    for (int mt = 0; mt < 2; mt++) {
        const int r0 = m0 + warp_m + mt * 16 + g;
#pragma unroll
        for (int nt = 0; nt < 8; nt++) {
            const int col = warp_n + nt * 8 + t * 2;
            const float b0 = biasc[col];
            const float b1 = biasc[col + 1];
            if (r0 < NN) {
                float2 o = make_float2(acc[mt][nt][0] + b0, acc[mt][nt][1] + b1);
                *reinterpret_cast<float2*>(out + (long)r0 * FF + col) = o;
            }
            if (r0 + 8 < NN) {
                float2 o = make_float2(acc[mt][nt][2] + b0, acc[mt][nt][3] + b1);
                *reinterpret_cast<float2*>(out + (long)(r0 + 8) * FF + col) = o;
            }
        }
    }
}

// ---------------- BatchNorm (training stats) + ReLU ----------------
#define BN_NB 200
__global__ void k_bn_part(const float* __restrict__ x1) {
    int b = blockIdx.x;
    int t = threadIdx.x;
    int per = (NN + BN_NB - 1) / BN_NB;
    int r0 = b * per;
    int r1 = (r0 + per < NN) ? r0 + per : NN;
    float s = 0.f, q = 0.f;
    for (int r = r0; r < r1; r++) {
        float v = x1[(long)r * FF + t];
        s += v;
        q += v * v;
    }
    d_bnpart[b * FF + t] = s;
    d_bnpart[BN_NB * FF + b * FF + t] = q;
}

__global__ void k_bn_final(const float* __restrict__ gamma, const float* __restrict__ beta) {
    int t = threadIdx.x;
    float s = 0.f, q = 0.f;
    for (int b = 0; b < BN_NB; b++) {
        s += d_bnpart[b * FF + t];
        q += d_bnpart[BN_NB * FF + b * FF + t];
    }
    float mean = s / (float)NN;
    float var = q / (float)NN - mean * mean;
    float inv = rsqrtf(var + EPSV);
    float sc = gamma[t] * inv;
    d_scale[t] = sc;
    d_shift[t] = beta[t] - mean * sc;
}

__global__ void k_bn_apply(const float* __restrict__ x1) {
    long i = (long)blockIdx.x * blockDim.x + threadIdx.x;
    if (i < (long)NN * FF) {
        int c = (int)(i & (FF - 1));
        float v = fmaxf(x1[i] * d_scale[c] + d_shift[c], 0.f);
        d_xr[i] = v;
        d_xrh[i] = __float2half(v);
    }
}

// ---------------- launch ----------------
extern "C" void kernel_launch(void* const* d_in, const int* in_sizes, int n_in,
                              void* d_out, int out_size) {
    const float* x      = (const float*)d_in[0];
    const int*   ei     = (const int*)d_in[1];
    const int*   etype  = (const int*)d_in[2];
    const float* comp1  = (const float*)d_in[3];
    const float* bases1 = (const float*)d_in[4];
    const float* root1  = (const float*)d_in[5];
    const float* bias1  = (const float*)d_in[6];
    const float* skip1w = (const float*)d_in[7];
    const float* skip1b = (const float*)d_in[8];
    const float* gamma  = (const float*)d_in[9];
    const float* beta   = (const float*)d_in[10];
    const float* comp2  = (const float*)d_in[11];
    const float* bases2 = (const float*)d_in[12];
    const float* root2  = (const float*)d_in[13];
    const float* bias2  = (const float*)d_in[14];
    const float* skip2w = (const float*)d_in[15];
    const float* skip2b = (const float*)d_in[16];

    float* h_out  = (float*)d_out;                // x1 pre-BN
    float* x2_out = (float*)d_out + (long)NN * FF;

    const int* src = ei;
    const int* dst = ei + EE;

    __half *accB, *xh, *xrh, *W1, *W2;
    float *xr, *bc1, *bc2;
    cudaGetSymbolAddress((void**)&accB, d_accB);
    cudaGetSymbolAddress((void**)&xh, d_xh);
    cudaGetSymbolAddress((void**)&xrh, d_xrh);
    cudaGetSymbolAddress((void**)&xr, d_xr);
    cudaGetSymbolAddress((void**)&W1, d_Wb1);
    cudaGetSymbolAddress((void**)&W2, d_Wb2);
    cudaGetSymbolAddress((void**)&bc1, d_biasc1);
    cudaGetSymbolAddress((void**)&bc2, d_biasc2);

    static bool attr_done = false;
    if (!attr_done) {
        cudaFuncSetAttribute(k_gemm_mma, cudaFuncAttributeMaxDynamicSharedMemorySize, GEMM_SMEM);
        attr_done = true;
    }

    const int EB = (EE + 255) / 256;
    const int NB = (NN * FF + 255) / 256;
    const int GEMM_GRID = (NN + 127) / 128;

    // ---- weight prep + input split (independent of graph) ----
    k_split_x<<<NB, 256>>>(x);
    k_prep<<<GK, FF>>>(root1, skip1w, bias1, skip1b, bases1, W1, bc1);
    k_prep<<<GK, FF>>>(root2, skip2w, bias2, skip2b, bases2, W2, bc2);

    // ---- CSR build (shared by both layers) ----
    k_zero_meta<<<1600, 256>>>();
    k_count<<<EB, 256>>>(dst, etype);
    k_scan_local<<<SCAN_NB, SCAN_CHUNK>>>();
    k_scan_chunks<<<1, 32>>>();
    k_scan_add<<<SCAN_NB, SCAN_CHUNK>>>();
    k_scatter<<<EB, 256>>>(src, dst, etype);

    // ---- layer 1 ----
    k_agg<<<NN, 128>>>(x, comp1);
    k_gemm_mma<<<GEMM_GRID, 256, GEMM_SMEM>>>(accB, xh, W1, bc1, h_out);

    // ---- BN + ReLU ----
    k_bn_part<<<BN_NB, FF>>>(h_out);
    k_bn_final<<<1, FF>>>(gamma, beta);
    k_bn_apply<<<NB, 256>>>(h_out);

    // ---- layer 2 ----
    k_agg<<<NN, 128>>>(xr, comp2);
    k_gemm_mma<<<GEMM_GRID, 256, GEMM_SMEM>>>(accB, xrh, W2, bc2, x2_out);
}

// round 13
// speedup vs baseline: 3.2323x; 1.0257x over previous
#include <cuda_runtime.h>
#include <cuda_fp16.h>
#include <cstdint>

// ---------------- problem constants ----------------
#define NN   50000
#define EE   800000
#define RR   8
#define BB   4
#define FF   128            // in = hidden = 128
#define KB   (BB*FF)        // 512, basis-contracted K
#define GK   640            // total GEMM K = 512 (accB) + 128 (x)
#define EPSV 1e-5f

// ---------------- scratch (static device globals; no allocs) ----------------
__device__ __half d_accB[NN * KB];    // aggregated messages, fp16
__device__ __half d_xh[NN * FF];      // fp16 of layer-1 input x
__device__ __half d_xrh[NN * FF];     // fp16 of relu(bn(x1))
__device__ __half d_Wb1[FF * GK];     // layer-1 weight, [n][k], fp16
__device__ __half d_Wb2[FF * GK];     // layer-2 weight
__device__ float d_biasc1[FF];
__device__ float d_biasc2[FF];
__device__ int   d_off[NN + 1];
__device__ int   d_cursor[NN];
__device__ int   d_cnt[NN * RR];
__device__ int   d_esort[EE];         // packed (etype<<20)|src
__device__ int   d_chunksum[64];
__device__ float d_bnpart[2 * 200 * FF];
__device__ float d_scale[FF];
__device__ float d_shift[FF];

// ---------------- helpers ----------------
__device__ __forceinline__ uint32_t smem_u32(const void* p) {
    uint32_t a;
    asm("{ .reg .u64 t; cvta.to.shared.u64 t, %1; cvt.u32.u64 %0, t; }" : "=r"(a) : "l"(p));
    return a;
}
__device__ __forceinline__ void cp16(uint32_t dst, const void* src, int szbytes) {
    asm volatile("cp.async.cg.shared.global [%0], [%1], 16, %2;"
                 :: "r"(dst), "l"(src), "r"(szbytes) : "memory");
}
#define CP_COMMIT() asm volatile("cp.async.commit_group;" ::: "memory")
#define CP_WAIT1()  asm volatile("cp.async.wait_group 1;" ::: "memory")
#define CP_WAIT0()  asm volatile("cp.async.wait_group 0;" ::: "memory")

#define LDSM4(R, addr)                                                        \
    asm volatile("ldmatrix.sync.aligned.m8n8.x4.shared.b16 {%0,%1,%2,%3}, [%4];" \
                 : "=r"((R)[0]), "=r"((R)[1]), "=r"((R)[2]), "=r"((R)[3])     \
                 : "r"(addr))

#define MMA_F16(acc, a, b)                                                    \
    asm volatile(                                                             \
        "mma.sync.aligned.m16n8k16.row.col.f32.f16.f16.f32 "                  \
        "{%0,%1,%2,%3}, {%4,%5,%6,%7}, {%8,%9}, {%0,%1,%2,%3};"               \
        : "+f"((acc)[0]), "+f"((acc)[1]), "+f"((acc)[2]), "+f"((acc)[3])      \
        : "r"((a)[0]), "r"((a)[1]), "r"((a)[2]), "r"((a)[3]),                 \
          "r"((b)[0]), "r"((b)[1]))

// ---------------- CSR build ----------------
__global__ void k_zero_meta() {
    int i = blockIdx.x * blockDim.x + threadIdx.x;
    int stride = gridDim.x * blockDim.x;
    for (int j = i; j < NN; j += stride) d_cursor[j] = 0;
    for (int j = i; j < NN * RR; j += stride) d_cnt[j] = 0;
}

__global__ void k_count(const int* __restrict__ dst, const int* __restrict__ et) {
    int e = blockIdx.x * blockDim.x + threadIdx.x;
    if (e < EE) atomicAdd(&d_cnt[dst[e] * RR + et[e]], 1);
}

#define SCAN_CHUNK 1024
#define SCAN_NB    49

__global__ void k_scan_local() {
    __shared__ int sh[SCAN_CHUNK];
    int i = blockIdx.x * SCAN_CHUNK + threadIdx.x;
    int v = 0;
    if (i < NN) {
#pragma unroll
        for (int r = 0; r < RR; r++) v += d_cnt[i * RR + r];
    }
    sh[threadIdx.x] = v;
    __syncthreads();
    for (int s = 1; s < SCAN_CHUNK; s <<= 1) {
        int t = (threadIdx.x >= s) ? sh[threadIdx.x - s] : 0;
        __syncthreads();
        sh[threadIdx.x] += t;
        __syncthreads();
    }
    if (i < NN) d_off[i] = sh[threadIdx.x] - v;
    if (threadIdx.x == SCAN_CHUNK - 1) d_chunksum[blockIdx.x] = sh[threadIdx.x];
}

__global__ void k_scan_chunks() {
    if (threadIdx.x == 0 && blockIdx.x == 0) {
        int acc = 0;
        for (int b = 0; b < SCAN_NB; b++) { int t = d_chunksum[b]; d_chunksum[b] = acc; acc += t; }
    }
}

__global__ void k_scan_add() {
    int i = blockIdx.x * SCAN_CHUNK + threadIdx.x;
    if (i < NN) d_off[i] += d_chunksum[blockIdx.x];
    if (i == 0) d_off[NN] = EE;
}

__global__ void k_scatter(const int* __restrict__ src, const int* __restrict__ dst,
                          const int* __restrict__ et) {
    int e = blockIdx.x * blockDim.x + threadIdx.x;
    if (e < EE) {
        int d = dst[e];
        int pos = d_off[d] + atomicAdd(&d_cursor[d], 1);
        d_esort[pos] = (et[e] << 20) | src[e];
    }
}

// ---------------- per-layer weight prep: [n][k] fp16 ----------------
__global__ void k_prep(const float* __restrict__ root, const float* __restrict__ skipw,
                       const float* __restrict__ bias, const float* __restrict__ skipb,
                       const float* __restrict__ bases,
                       __half* __restrict__ Wh, float* __restrict__ biasc) {
    int k = blockIdx.x;
    int n = threadIdx.x;
    float w = (k < KB) ? bases[k * FF + n]
                       : root[(k - KB) * FF + n] + skipw[(k - KB) * FF + n];
    Wh[n * GK + k] = __float2half(w);
    if (k == 0) biasc[n] = bias[n] + skipb[n];
}

// ---------------- fp32 -> fp16 ----------------
__global__ void k_split_x(const float* __restrict__ x) {
    long i = (long)blockIdx.x * blockDim.x + threadIdx.x;
    if (i < (long)NN * FF) d_xh[i] = __float2half(x[i]);
}

// ---------------- aggregation: one block (128 thr) per node, fp16 gather ----------------
__global__ void __launch_bounds__(128) k_agg(const __half* __restrict__ xin,
                                             const float* __restrict__ comp) {
    __shared__ float sc[RR * BB];
    int node = blockIdx.x;
    int t = threadIdx.x;
    if (t < RR * BB) {
        int r = t >> 2;
        float c = (float)d_cnt[node * RR + r];
        sc[t] = comp[t] / fmaxf(c, 1.0f);
    }
    __syncthreads();
    int s = d_off[node], e = d_off[node + 1];
    float a0 = 0.f, a1 = 0.f, a2 = 0.f, a3 = 0.f;
    int i = s;
    for (; i + 8 <= e; i += 8) {
        int   p[8];
        float v[8];
#pragma unroll
        for (int j = 0; j < 8; j++) p[j] = d_esort[i + j];
#pragma unroll
        for (int j = 0; j < 8; j++)
            v[j] = __half2float(xin[(p[j] & 0xFFFFF) * FF + t]);
#pragma unroll
        for (int j = 0; j < 8; j++) {
            int r = p[j] >> 20;
            a0 += v[j] * sc[r * 4 + 0];
            a1 += v[j] * sc[r * 4 + 1];
            a2 += v[j] * sc[r * 4 + 2];
            a3 += v[j] * sc[r * 4 + 3];
        }
    }
    for (; i < e; i++) {
        int p = d_esort[i];
        int r = p >> 20;
        float v = __half2float(xin[(p & 0xFFFFF) * FF + t]);
        a0 += v * sc[r * 4 + 0];
        a1 += v * sc[r * 4 + 1];
        a2 += v * sc[r * 4 + 2];
        a3 += v * sc[r * 4 + 3];
    }
    long base = (long)node * KB + t;
    d_accB[base + 0 * FF] = __float2half(a0);
    d_accB[base + 1 * FF] = __float2half(a1);
    d_accB[base + 2 * FF] = __float2half(a2);
    d_accB[base + 3 * FF] = __float2half(a3);
}

// ---------------- mma.sync fp16 GEMM (single term) + ldmatrix ----------------
// out[m][n] = sum_k A[m][k]*W[k][n] + biasc[n];  A = [accB | x], K = 640
// CTA tile 128x128, BK=32, 8 warps (4 M x 2 N), warp tile 32x64, 2 CTAs/SM.
// SMEM per stage: A, B tiles of 128x32 fp16 (8KB each) = 16KB; 2 stages.
// Swizzle: 64B rows; 16B slot = (chunk ^ ((row>>1)&3)).
#define BKC     32
#define NCHUNK  20
#define TILE_B  8192
#define STAGE_B 16384
#define GEMM_SMEM (2 * STAGE_B)

__device__ __forceinline__ void prefetch_chunk(
        int cNum, uint32_t sbase, int m0, int tid,
        const __half* Ah, const __half* AtH, const __half* Bh) {
    const __half* ah;
    int lda, kofs;
    if (cNum < 16) { ah = Ah;  lda = KB; kofs = cNum * BKC; }
    else           { ah = AtH; lda = FF; kofs = (cNum - 16) * BKC; }
#pragma unroll
    for (int i = 0; i < 2; i++) {
        int idx = tid + i * 256;        // 0..511
        int r = idx >> 2;               // 0..127
        int c = idx & 3;                // 16B chunk within 64B row
        uint32_t dst = sbase + r * 64 + ((c ^ ((r >> 1) & 3)) << 4);
        int gr = m0 + r;
        int sz = (gr < NN) ? 16 : 0;
        int grc = (gr < NN) ? gr : 0;
        long aofs = (long)grc * lda + kofs + c * 8;
        cp16(dst, ah + aofs, sz);
        long bofs = (long)r * GK + cNum * BKC + c * 8;
        cp16(dst + TILE_B, Bh + bofs, 16);
    }
}

__global__ void __launch_bounds__(256, 2) k_gemm_mma(
        const __half* __restrict__ Ah, const __half* __restrict__ AtH,
        const __half* __restrict__ Bh,
        const float* __restrict__ biasc,
        float* __restrict__ out) {
    extern __shared__ float4 smem_raw[];
    uint32_t sm0 = smem_u32(smem_raw);
    const int tid = threadIdx.x;
    const int wid = tid >> 5;
    const int lane = tid & 31;
    const int m0 = blockIdx.x * 128;
    const int warp_m = (wid & 3) * 32;
    const int warp_n = (wid >> 2) * 64;
    const int g = lane >> 2;
    const int t = lane & 3;
    const int rr = lane & 7;
    const int mid = lane >> 3;

    float acc[2][8][4];
#pragma unroll
    for (int mt = 0; mt < 2; mt++)
#pragma unroll
        for (int nt = 0; nt < 8; nt++)
#pragma unroll
            for (int q = 0; q < 4; q++) acc[mt][nt][q] = 0.f;

    prefetch_chunk(0, sm0, m0, tid, Ah, AtH, Bh);
    CP_COMMIT();

#pragma unroll 1
    for (int c = 0; c < NCHUNK; c++) {
        if (c + 1 < NCHUNK) {
            prefetch_chunk(c + 1, sm0 + ((c + 1) & 1) * STAGE_B, m0, tid, Ah, AtH, Bh);
            CP_COMMIT();
            CP_WAIT1();
        } else {
            CP_WAIT0();
        }
        __syncthreads();
        const uint32_t su = sm0 + (c & 1) * STAGE_B;
#pragma unroll
        for (int s = 0; s < 2; s++) {
            const int c0 = s * 2;
            // ---- A fragments via ldmatrix.x4 ----
            uint32_t a_h[2][4];
#pragma unroll
            for (int mt = 0; mt < 2; mt++) {
                int arow = warp_m + mt * 16 + ((mid & 1) << 3) + rr;
                int achk = c0 + (mid >> 1);
                uint32_t aaddr = su + arow * 64 + (((achk ^ ((arow >> 1) & 3))) << 4);
                LDSM4(a_h[mt], aaddr);
            }
            // ---- B in pairs of n-tiles via ldmatrix.x4 ----
#pragma unroll
            for (int p = 0; p < 4; p++) {
                int brow = warp_n + (p * 2 + (mid >> 1)) * 8 + rr;
                int bchk = c0 + (mid & 1);
                uint32_t baddr = su + TILE_B + brow * 64 +
                                 (((bchk ^ ((brow >> 1) & 3))) << 4);
                uint32_t bh4[4];
                LDSM4(bh4, baddr);
#pragma unroll
                for (int q = 0; q < 2; q++) {
                    const int nt = p * 2 + q;
                    uint32_t bhq[2] = {bh4[q * 2], bh4[q * 2 + 1]};
#pragma unroll
                    for (int mt = 0; mt < 2; mt++) {
                        MMA_F16(acc[mt][nt], a_h[mt], bhq);
                    }
                }
            }
        }
        __syncthreads();
    }

    // epilogue: bias + store
#pragma unroll
    for (int mt = 0; mt < 2; mt++) {
        const int r0 = m0 + warp_m + mt * 16 + g;
#pragma unroll
        for (int nt = 0; nt < 8; nt++) {
            const int col = warp_n + nt * 8 + t * 2;
            const float b0 = biasc[col];
            const float b1 = biasc[col + 1];
            if (r0 < NN) {
                float2 o = make_float2(acc[mt][nt][0] + b0, acc[mt][nt][1] + b1);
                *reinterpret_cast<float2*>(out + (long)r0 * FF + col) = o;
            }
            if (r0 + 8 < NN) {
                float2 o = make_float2(acc[mt][nt][2] + b0, acc[mt][nt][3] + b1);
                *reinterpret_cast<float2*>(out + (long)(r0 + 8) * FF + col) = o;
            }
        }
    }
}

// ---------------- BatchNorm (training stats) + ReLU ----------------
#define BN_NB 200
__global__ void k_bn_part(const float* __restrict__ x1) {
    int b = blockIdx.x;
    int t = threadIdx.x;
    int per = (NN + BN_NB - 1) / BN_NB;
    int r0 = b * per;
    int r1 = (r0 + per < NN) ? r0 + per : NN;
    float s = 0.f, q = 0.f;
    for (int r = r0; r < r1; r++) {
        float v = x1[(long)r * FF + t];
        s += v;
        q += v * v;
    }
    d_bnpart[b * FF + t] = s;
    d_bnpart[BN_NB * FF + b * FF + t] = q;
}

__global__ void k_bn_final(const float* __restrict__ gamma, const float* __restrict__ beta) {
    int t = threadIdx.x;
    float s = 0.f, q = 0.f;
    for (int b = 0; b < BN_NB; b++) {
        s += d_bnpart[b * FF + t];
        q += d_bnpart[BN_NB * FF + b * FF + t];
    }
    float mean = s / (float)NN;
    float var = q / (float)NN - mean * mean;
    float inv = rsqrtf(var + EPSV);
    float sc = gamma[t] * inv;
    d_scale[t] = sc;
    d_shift[t] = beta[t] - mean * sc;
}

__global__ void k_bn_apply(const float* __restrict__ x1) {
    long i = (long)blockIdx.x * blockDim.x + threadIdx.x;
    if (i < (long)NN * FF) {
        int c = (int)(i & (FF - 1));
        float v = fmaxf(x1[i] * d_scale[c] + d_shift[c], 0.f);
        d_xrh[i] = __float2half(v);
    }
}

// ---------------- launch ----------------
extern "C" void kernel_launch(void* const* d_in, const int* in_sizes, int n_in,
                              void* d_out, int out_size) {
    const float* x      = (const float*)d_in[0];
    const int*   ei     = (const int*)d_in[1];
    const int*   etype  = (const int*)d_in[2];
    const float* comp1  = (const float*)d_in[3];
    const float* bases1 = (const float*)d_in[4];
    const float* root1  = (const float*)d_in[5];
    const float* bias1  = (const float*)d_in[6];
    const float* skip1w = (const float*)d_in[7];
    const float* skip1b = (const float*)d_in[8];
    const float* gamma  = (const float*)d_in[9];
    const float* beta   = (const float*)d_in[10];
    const float* comp2  = (const float*)d_in[11];
    const float* bases2 = (const float*)d_in[12];
    const float* root2  = (const float*)d_in[13];
    const float* bias2  = (const float*)d_in[14];
    const float* skip2w = (const float*)d_in[15];
    const float* skip2b = (const float*)d_in[16];

    float* h_out  = (float*)d_out;                // x1 pre-BN
    float* x2_out = (float*)d_out + (long)NN * FF;

    const int* src = ei;
    const int* dst = ei + EE;

    __half *accB, *xh, *xrh, *W1, *W2;
    float *bc1, *bc2;
    cudaGetSymbolAddress((void**)&accB, d_accB);
    cudaGetSymbolAddress((void**)&xh, d_xh);
    cudaGetSymbolAddress((void**)&xrh, d_xrh);
    cudaGetSymbolAddress((void**)&W1, d_Wb1);
    cudaGetSymbolAddress((void**)&W2, d_Wb2);
    cudaGetSymbolAddress((void**)&bc1, d_biasc1);
    cudaGetSymbolAddress((void**)&bc2, d_biasc2);

    static bool attr_done = false;
    if (!attr_done) {
        cudaFuncSetAttribute(k_gemm_mma, cudaFuncAttributeMaxDynamicSharedMemorySize, GEMM_SMEM);
        attr_done = true;
    }

    const int EB = (EE + 255) / 256;
    const int NB = (NN * FF + 255) / 256;
    const int GEMM_GRID = (NN + 127) / 128;

    // ---- weight prep + input split (independent of graph) ----
    k_split_x<<<NB, 256>>>(x);
    k_prep<<<GK, FF>>>(root1, skip1w, bias1, skip1b, bases1, W1, bc1);
    k_prep<<<GK, FF>>>(root2, skip2w, bias2, skip2b, bases2, W2, bc2);

    // ---- CSR build (shared by both layers) ----
    k_zero_meta<<<1600, 256>>>();
    k_count<<<EB, 256>>>(dst, etype);
    k_scan_local<<<SCAN_NB, SCAN_CHUNK>>>();
    k_scan_chunks<<<1, 32>>>();
    k_scan_add<<<SCAN_NB, SCAN_CHUNK>>>();
    k_scatter<<<EB, 256>>>(src, dst, etype);

    // ---- layer 1 ----
    k_agg<<<NN, 128>>>(xh, comp1);
    k_gemm_mma<<<GEMM_GRID, 256, GEMM_SMEM>>>(accB, xh, W1, bc1, h_out);

    // ---- BN + ReLU ----
    k_bn_part<<<BN_NB, FF>>>(h_out);
    k_bn_final<<<1, FF>>>(gamma, beta);
    k_bn_apply<<<NB, 256>>>(h_out);

    // ---- layer 2 ----
    k_agg<<<NN, 128>>>(xrh, comp2);
    k_gemm_mma<<<GEMM_GRID, 256, GEMM_SMEM>>>(accB, xrh, W2, bc2, x2_out);
}

// round 14
// speedup vs baseline: 3.8714x; 1.1977x over previous
#include <cuda_runtime.h>
#include <cuda_fp16.h>
#include <cstdint>

// ---------------- problem constants ----------------
#define NN   50000
#define EE   800000
#define RR   8
#define BB   4
#define FF   128            // in = hidden = 128
#define KB   (BB*FF)        // 512, basis-contracted K
#define GK   640            // total GEMM K = 512 (accB) + 128 (x)
#define EPSV 1e-5f

// ---------------- scratch (static device globals; no allocs) ----------------
__device__ __half d_accB[NN * KB];    // aggregated messages, fp16
__device__ __half d_xh[NN * FF];      // fp16 of layer-1 input x
__device__ __half d_xrh[NN * FF];     // fp16 of relu(bn(x1))
__device__ __half d_Wb1[FF * GK];     // layer-1 weight, [n][k], fp16
__device__ __half d_Wb2[FF * GK];     // layer-2 weight
__device__ float d_biasc1[FF];
__device__ float d_biasc2[FF];
__device__ int   d_off[NN + 1];
__device__ int   d_cursor[NN];
__device__ int   d_cnt[NN * RR];
__device__ int   d_esort[EE];         // packed (etype<<20)|src
__device__ int   d_chunksum[64];
__device__ float d_bnpart[2 * 200 * FF];
__device__ float d_scale[FF];
__device__ float d_shift[FF];

// ---------------- helpers ----------------
__device__ __forceinline__ uint32_t smem_u32(const void* p) {
    uint32_t a;
    asm("{ .reg .u64 t; cvta.to.shared.u64 t, %1; cvt.u32.u64 %0, t; }" : "=r"(a) : "l"(p));
    return a;
}
__device__ __forceinline__ void cp16(uint32_t dst, const void* src, int szbytes) {
    asm volatile("cp.async.cg.shared.global [%0], [%1], 16, %2;"
                 :: "r"(dst), "l"(src), "r"(szbytes) : "memory");
}
#define CP_COMMIT() asm volatile("cp.async.commit_group;" ::: "memory")
#define CP_WAIT1()  asm volatile("cp.async.wait_group 1;" ::: "memory")
#define CP_WAIT0()  asm volatile("cp.async.wait_group 0;" ::: "memory")

#define LDSM4(R, addr)                                                        \
    asm volatile("ldmatrix.sync.aligned.m8n8.x4.shared.b16 {%0,%1,%2,%3}, [%4];" \
                 : "=r"((R)[0]), "=r"((R)[1]), "=r"((R)[2]), "=r"((R)[3])     \
                 : "r"(addr))

#define MMA_F16(acc, a, b)                                                    \
    asm volatile(                                                             \
        "mma.sync.aligned.m16n8k16.row.col.f32.f16.f16.f32 "                  \
        "{%0,%1,%2,%3}, {%4,%5,%6,%7}, {%8,%9}, {%0,%1,%2,%3};"               \
        : "+f"((acc)[0]), "+f"((acc)[1]), "+f"((acc)[2]), "+f"((acc)[3])      \
        : "r"((a)[0]), "r"((a)[1]), "r"((a)[2]), "r"((a)[3]),                 \
          "r"((b)[0]), "r"((b)[1]))

// ---------------- CSR build ----------------
__global__ void k_zero_meta() {
    int i = blockIdx.x * blockDim.x + threadIdx.x;
    int stride = gridDim.x * blockDim.x;
    for (int j = i; j < NN; j += stride) d_cursor[j] = 0;
    for (int j = i; j < NN * RR; j += stride) d_cnt[j] = 0;
}

__global__ void k_count(const int* __restrict__ dst, const int* __restrict__ et) {
    int e = blockIdx.x * blockDim.x + threadIdx.x;
    if (e < EE) atomicAdd(&d_cnt[dst[e] * RR + et[e]], 1);
}

#define SCAN_CHUNK 1024
#define SCAN_NB    49

__global__ void k_scan_local() {
    __shared__ int sh[SCAN_CHUNK];
    int i = blockIdx.x * SCAN_CHUNK + threadIdx.x;
    int v = 0;
    if (i < NN) {
#pragma unroll
        for (int r = 0; r < RR; r++) v += d_cnt[i * RR + r];
    }
    sh[threadIdx.x] = v;
    __syncthreads();
    for (int s = 1; s < SCAN_CHUNK; s <<= 1) {
        int t = (threadIdx.x >= s) ? sh[threadIdx.x - s] : 0;
        __syncthreads();
        sh[threadIdx.x] += t;
        __syncthreads();
    }
    if (i < NN) d_off[i] = sh[threadIdx.x] - v;
    if (threadIdx.x == SCAN_CHUNK - 1) d_chunksum[blockIdx.x] = sh[threadIdx.x];
}

// warp scan over the 49 chunk sums (lane covers idx l and l+32)
__global__ void k_scan_chunks() {
    int l = threadIdx.x;           // 32 threads
    int a = (l < SCAN_NB) ? d_chunksum[l] : 0;
    int b = (l + 32 < SCAN_NB) ? d_chunksum[l + 32] : 0;
    int sa = a, sb = b;
#pragma unroll
    for (int o = 1; o < 32; o <<= 1) {
        int ta = __shfl_up_sync(0xFFFFFFFF, sa, o);
        int tb = __shfl_up_sync(0xFFFFFFFF, sb, o);
        if (l >= o) { sa += ta; sb += tb; }
    }
    int totA = __shfl_sync(0xFFFFFFFF, sa, 31);
    if (l < SCAN_NB) d_chunksum[l] = sa - a;
    if (l + 32 < SCAN_NB) d_chunksum[l + 32] = totA + sb - b;
}

__global__ void k_scan_add() {
    int i = blockIdx.x * SCAN_CHUNK + threadIdx.x;
    if (i < NN) d_off[i] += d_chunksum[blockIdx.x];
    if (i == 0) d_off[NN] = EE;
}

__global__ void k_scatter(const int* __restrict__ src, const int* __restrict__ dst,
                          const int* __restrict__ et) {
    int e = blockIdx.x * blockDim.x + threadIdx.x;
    if (e < EE) {
        int d = dst[e];
        int pos = d_off[d] + atomicAdd(&d_cursor[d], 1);
        d_esort[pos] = (et[e] << 20) | src[e];
    }
}

// ---------------- per-layer weight prep: [n][k] fp16 ----------------
__global__ void k_prep(const float* __restrict__ root, const float* __restrict__ skipw,
                       const float* __restrict__ bias, const float* __restrict__ skipb,
                       const float* __restrict__ bases,
                       __half* __restrict__ Wh, float* __restrict__ biasc) {
    int k = blockIdx.x;
    int n = threadIdx.x;
    float w = (k < KB) ? bases[k * FF + n]
                       : root[(k - KB) * FF + n] + skipw[(k - KB) * FF + n];
    Wh[n * GK + k] = __float2half(w);
    if (k == 0) biasc[n] = bias[n] + skipb[n];
}

// ---------------- fp32 -> fp16 ----------------
__global__ void k_split_x(const float* __restrict__ x) {
    long i = (long)blockIdx.x * blockDim.x + threadIdx.x;
    if (i < (long)NN * FF) d_xh[i] = __float2half(x[i]);
}

// ---------------- aggregation: one WARP per node, fp16 gather ----------------
// lane owns features lane*4..lane*4+3; acc[b][f] over edges.
__global__ void __launch_bounds__(256) k_agg(const __half* __restrict__ xin,
                                             const float* __restrict__ comp) {
    __shared__ __align__(16) float s_sc[8][32];   // per-warp sc[r][b]
    const int warp = threadIdx.x >> 5;
    const int lane = threadIdx.x & 31;
    const int node = blockIdx.x * 8 + warp;       // 6250*8 = 50000 exact

    // sc[lane] = comp[lane] / max(cnt[node][lane>>2],1)
    {
        int r = lane >> 2;
        float c = (float)d_cnt[node * RR + r];
        s_sc[warp][lane] = comp[lane] / fmaxf(c, 1.0f);
    }
    __syncwarp();

    const int s = d_off[node], e = d_off[node + 1];
    float acc[4][4];
#pragma unroll
    for (int b = 0; b < 4; b++)
#pragma unroll
        for (int f = 0; f < 4; f++) acc[b][f] = 0.f;

    const uint2* xbase = reinterpret_cast<const uint2*>(xin) ;
    int i = s;
    for (; i + 4 <= e; i += 4) {
        int p[4];
        uint2 u[4];
#pragma unroll
        for (int j = 0; j < 4; j++) p[j] = d_esort[i + j];
#pragma unroll
        for (int j = 0; j < 4; j++)
            u[j] = xbase[(long)(p[j] & 0xFFFFF) * (FF / 4) + lane];
#pragma unroll
        for (int j = 0; j < 4; j++) {
            int r = p[j] >> 20;
            float4 sc4 = *reinterpret_cast<const float4*>(&s_sc[warp][r * 4]);
            half2 h01 = *reinterpret_cast<half2*>(&u[j].x);
            half2 h23 = *reinterpret_cast<half2*>(&u[j].y);
            float v0 = __low2float(h01), v1 = __high2float(h01);
            float v2 = __low2float(h23), v3 = __high2float(h23);
            acc[0][0] += v0 * sc4.x; acc[0][1] += v1 * sc4.x;
            acc[0][2] += v2 * sc4.x; acc[0][3] += v3 * sc4.x;
            acc[1][0] += v0 * sc4.y; acc[1][1] += v1 * sc4.y;
            acc[1][2] += v2 * sc4.y; acc[1][3] += v3 * sc4.y;
            acc[2][0] += v0 * sc4.z; acc[2][1] += v1 * sc4.z;
            acc[2][2] += v2 * sc4.z; acc[2][3] += v3 * sc4.z;
            acc[3][0] += v0 * sc4.w; acc[3][1] += v1 * sc4.w;
            acc[3][2] += v2 * sc4.w; acc[3][3] += v3 * sc4.w;
        }
    }
    for (; i < e; i++) {
        int p = d_esort[i];
        int r = p >> 20;
        float4 sc4 = *reinterpret_cast<const float4*>(&s_sc[warp][r * 4]);
        uint2 u = xbase[(long)(p & 0xFFFFF) * (FF / 4) + lane];
        half2 h01 = *reinterpret_cast<half2*>(&u.x);
        half2 h23 = *reinterpret_cast<half2*>(&u.y);
        float v0 = __low2float(h01), v1 = __high2float(h01);
        float v2 = __low2float(h23), v3 = __high2float(h23);
        acc[0][0] += v0 * sc4.x; acc[0][1] += v1 * sc4.x;
        acc[0][2] += v2 * sc4.x; acc[0][3] += v3 * sc4.x;
        acc[1][0] += v0 * sc4.y; acc[1][1] += v1 * sc4.y;
        acc[1][2] += v2 * sc4.y; acc[1][3] += v3 * sc4.y;
        acc[2][0] += v0 * sc4.z; acc[2][1] += v1 * sc4.z;
        acc[2][2] += v2 * sc4.z; acc[2][3] += v3 * sc4.z;
        acc[3][0] += v0 * sc4.w; acc[3][1] += v1 * sc4.w;
        acc[3][2] += v2 * sc4.w; acc[3][3] += v3 * sc4.w;
    }

    // store: accB[node][b*FF + lane*4 .. +3] as uint2 per b
    uint2* obase = reinterpret_cast<uint2*>(d_accB + (long)node * KB);
#pragma unroll
    for (int b = 0; b < 4; b++) {
        half2 o01 = __floats2half2_rn(acc[b][0], acc[b][1]);
        half2 o23 = __floats2half2_rn(acc[b][2], acc[b][3]);
        uint2 o;
        o.x = *reinterpret_cast<uint32_t*>(&o01);
        o.y = *reinterpret_cast<uint32_t*>(&o23);
        obase[b * (FF / 4) + lane] = o;
    }
}

// ---------------- mma.sync fp16 GEMM (single term) + ldmatrix ----------------
// out[m][n] = sum_k A[m][k]*W[k][n] + biasc[n];  A = [accB | x], K = 640
// CTA tile 128x128, BK=32, 8 warps (4 M x 2 N), warp tile 32x64, 2 CTAs/SM.
// SMEM per stage: A, B tiles of 128x32 fp16 (8KB each) = 16KB; 2 stages.
// Swizzle: 64B rows; 16B slot = (chunk ^ ((row>>1)&3)).
#define BKC     32
#define NCHUNK  20
#define TILE_B  8192
#define STAGE_B 16384
#define GEMM_SMEM (2 * STAGE_B)

__device__ __forceinline__ void prefetch_chunk(
        int cNum, uint32_t sbase, int m0, int tid,
        const __half* Ah, const __half* AtH, const __half* Bh) {
    const __half* ah;
    int lda, kofs;
    if (cNum < 16) { ah = Ah;  lda = KB; kofs = cNum * BKC; }
    else           { ah = AtH; lda = FF; kofs = (cNum - 16) * BKC; }
#pragma unroll
    for (int i = 0; i < 2; i++) {
        int idx = tid + i * 256;        // 0..511
        int r = idx >> 2;               // 0..127
        int c = idx & 3;                // 16B chunk within 64B row
        uint32_t dst = sbase + r * 64 + ((c ^ ((r >> 1) & 3)) << 4);
        int gr = m0 + r;
        int sz = (gr < NN) ? 16 : 0;
        int grc = (gr < NN) ? gr : 0;
        long aofs = (long)grc * lda + kofs + c * 8;
        cp16(dst, ah + aofs, sz);
        long bofs = (long)r * GK + cNum * BKC + c * 8;
        cp16(dst + TILE_B, Bh + bofs, 16);
    }
}

__global__ void __launch_bounds__(256, 2) k_gemm_mma(
        const __half* __restrict__ Ah, const __half* __restrict__ AtH,
        const __half* __restrict__ Bh,
        const float* __restrict__ biasc,
        float* __restrict__ out) {
    extern __shared__ float4 smem_raw[];
    uint32_t sm0 = smem_u32(smem_raw);
    const int tid = threadIdx.x;
    const int wid = tid >> 5;
    const int lane = tid & 31;
    const int m0 = blockIdx.x * 128;
    const int warp_m = (wid & 3) * 32;
    const int warp_n = (wid >> 2) * 64;
    const int g = lane >> 2;
    const int t = lane & 3;
    const int rr = lane & 7;
    const int mid = lane >> 3;

    float acc[2][8][4];
#pragma unroll
    for (int mt = 0; mt < 2; mt++)
#pragma unroll
        for (int nt = 0; nt < 8; nt++)
#pragma unroll
            for (int q = 0; q < 4; q++) acc[mt][nt][q] = 0.f;

    prefetch_chunk(0, sm0, m0, tid, Ah, AtH, Bh);
    CP_COMMIT();

#pragma unroll 1
    for (int c = 0; c < NCHUNK; c++) {
        if (c + 1 < NCHUNK) {
            prefetch_chunk(c + 1, sm0 + ((c + 1) & 1) * STAGE_B, m0, tid, Ah, AtH, Bh);
            CP_COMMIT();
            CP_WAIT1();
        } else {
            CP_WAIT0();
        }
        __syncthreads();
        const uint32_t su = sm0 + (c & 1) * STAGE_B;
#pragma unroll
        for (int s = 0; s < 2; s++) {
            const int c0 = s * 2;
            // ---- A fragments via ldmatrix.x4 ----
            uint32_t a_h[2][4];
#pragma unroll
            for (int mt = 0; mt < 2; mt++) {
                int arow = warp_m + mt * 16 + ((mid & 1) << 3) + rr;
                int achk = c0 + (mid >> 1);
                uint32_t aaddr = su + arow * 64 + (((achk ^ ((arow >> 1) & 3))) << 4);
                LDSM4(a_h[mt], aaddr);
            }
            // ---- B in pairs of n-tiles via ldmatrix.x4 ----
#pragma unroll
            for (int p = 0; p < 4; p++) {
                int brow = warp_n + (p * 2 + (mid >> 1)) * 8 + rr;
                int bchk = c0 + (mid & 1);
                uint32_t baddr = su + TILE_B + brow * 64 +
                                 (((bchk ^ ((brow >> 1) & 3))) << 4);
                uint32_t bh4[4];
                LDSM4(bh4, baddr);
#pragma unroll
                for (int q = 0; q < 2; q++) {
                    const int nt = p * 2 + q;
                    uint32_t bhq[2] = {bh4[q * 2], bh4[q * 2 + 1]};
#pragma unroll
                    for (int mt = 0; mt < 2; mt++) {
                        MMA_F16(acc[mt][nt], a_h[mt], bhq);
                    }
                }
            }
        }
        __syncthreads();
    }

    // epilogue: bias + store
#pragma unroll
    for (int mt = 0; mt < 2; mt++) {
        const int r0 = m0 + warp_m + mt * 16 + g;
#pragma unroll
        for (int nt = 0; nt < 8; nt++) {
            const int col = warp_n + nt * 8 + t * 2;
            const float b0 = biasc[col];
            const float b1 = biasc[col + 1];
            if (r0 < NN) {
                float2 o = make_float2(acc[mt][nt][0] + b0, acc[mt][nt][1] + b1);
                *reinterpret_cast<float2*>(out + (long)r0 * FF + col) = o;
            }
            if (r0 + 8 < NN) {
                float2 o = make_float2(acc[mt][nt][2] + b0, acc[mt][nt][3] + b1);
                *reinterpret_cast<float2*>(out + (long)(r0 + 8) * FF + col) = o;
            }
        }
    }
}

// ---------------- BatchNorm (training stats) + ReLU ----------------
#define BN_NB 200
__global__ void k_bn_part(const float* __restrict__ x1) {
    int b = blockIdx.x;
    int t = threadIdx.x;
    int per = (NN + BN_NB - 1) / BN_NB;
    int r0 = b * per;
    int r1 = (r0 + per < NN) ? r0 + per : NN;
    float s = 0.f, q = 0.f;
    for (int r = r0; r < r1; r++) {
        float v = x1[(long)r * FF + t];
        s += v;
        q += v * v;
    }
    d_bnpart[b * FF + t] = s;
    d_bnpart[BN_NB * FF + b * FF + t] = q;
}

__global__ void k_bn_final(const float* __restrict__ gamma, const float* __restrict__ beta) {
    int t = threadIdx.x;
    float s = 0.f, q = 0.f;
    for (int b = 0; b < BN_NB; b++) {
        s += d_bnpart[b * FF + t];
        q += d_bnpart[BN_NB * FF + b * FF + t];
    }
    float mean = s / (float)NN;
    float var = q / (float)NN - mean * mean;
    float inv = rsqrtf(var + EPSV);
    float sc = gamma[t] * inv;
    d_scale[t] = sc;
    d_shift[t] = beta[t] - mean * sc;
}

__global__ void k_bn_apply(const float* __restrict__ x1) {
    long i = (long)blockIdx.x * blockDim.x + threadIdx.x;
    if (i < (long)NN * FF) {
        int c = (int)(i & (FF - 1));
        float v = fmaxf(x1[i] * d_scale[c] + d_shift[c], 0.f);
        d_xrh[i] = __float2half(v);
    }
}

// ---------------- launch ----------------
extern "C" void kernel_launch(void* const* d_in, const int* in_sizes, int n_in,
                              void* d_out, int out_size) {
    const float* x      = (const float*)d_in[0];
    const int*   ei     = (const int*)d_in[1];
    const int*   etype  = (const int*)d_in[2];
    const float* comp1  = (const float*)d_in[3];
    const float* bases1 = (const float*)d_in[4];
    const float* root1  = (const float*)d_in[5];
    const float* bias1  = (const float*)d_in[6];
    const float* skip1w = (const float*)d_in[7];
    const float* skip1b = (const float*)d_in[8];
    const float* gamma  = (const float*)d_in[9];
    const float* beta   = (const float*)d_in[10];
    const float* comp2  = (const float*)d_in[11];
    const float* bases2 = (const float*)d_in[12];
    const float* root2  = (const float*)d_in[13];
    const float* bias2  = (const float*)d_in[14];
    const float* skip2w = (const float*)d_in[15];
    const float* skip2b = (const float*)d_in[16];

    float* h_out  = (float*)d_out;                // x1 pre-BN
    float* x2_out = (float*)d_out + (long)NN * FF;

    const int* src = ei;
    const int* dst = ei + EE;

    __half *accB, *xh, *xrh, *W1, *W2;
    float *bc1, *bc2;
    cudaGetSymbolAddress((void**)&accB, d_accB);
    cudaGetSymbolAddress((void**)&xh, d_xh);
    cudaGetSymbolAddress((void**)&xrh, d_xrh);
    cudaGetSymbolAddress((void**)&W1, d_Wb1);
    cudaGetSymbolAddress((void**)&W2, d_Wb2);
    cudaGetSymbolAddress((void**)&bc1, d_biasc1);
    cudaGetSymbolAddress((void**)&bc2, d_biasc2);

    static bool attr_done = false;
    if (!attr_done) {
        cudaFuncSetAttribute(k_gemm_mma, cudaFuncAttributeMaxDynamicSharedMemorySize, GEMM_SMEM);
        attr_done = true;
    }

    const int EB = (EE + 255) / 256;
    const int NB = (NN * FF + 255) / 256;
    const int GEMM_GRID = (NN + 127) / 128;
    const int AGG_GRID = NN / 8;                  // 6250, exact

    // ---- weight prep + input split (independent of graph) ----
    k_split_x<<<NB, 256>>>(x);
    k_prep<<<GK, FF>>>(root1, skip1w, bias1, skip1b, bases1, W1, bc1);
    k_prep<<<GK, FF>>>(root2, skip2w, bias2, skip2b, bases2, W2, bc2);

    // ---- CSR build (shared by both layers) ----
    k_zero_meta<<<1600, 256>>>();
    k_count<<<EB, 256>>>(dst, etype);
    k_scan_local<<<SCAN_NB, SCAN_CHUNK>>>();
    k_scan_chunks<<<1, 32>>>();
    k_scan_add<<<SCAN_NB, SCAN_CHUNK>>>();
    k_scatter<<<EB, 256>>>(src, dst, etype);

    // ---- layer 1 ----
    k_agg<<<AGG_GRID, 256>>>(xh, comp1);
    k_gemm_mma<<<GEMM_GRID, 256, GEMM_SMEM>>>(accB, xh, W1, bc1, h_out);

    // ---- BN + ReLU ----
    k_bn_part<<<BN_NB, FF>>>(h_out);
    k_bn_final<<<1, FF>>>(gamma, beta);
    k_bn_apply<<<NB, 256>>>(h_out);

    // ---- layer 2 ----
    k_agg<<<AGG_GRID, 256>>>(xrh, comp2);
    k_gemm_mma<<<GEMM_GRID, 256, GEMM_SMEM>>>(accB, xrh, W2, bc2, x2_out);
}